// round 6
// baseline (speedup 1.0000x reference)
#include <cuda_runtime.h>
#include <cuda_bf16.h>
#include <cstdint>

// Problem constants
#define TSEQ 1024
#define BATCH 64
#define HID 128
#define G4 512            // 4*HID
#define XGHALF (TSEQ*BATCH*G4)   // per-direction xg elements

// ---------------- scratch (static device globals; no allocations) -------------
__device__ float g_xt[TSEQ * BATCH * 128];        // x transposed to [T,B,128]
__device__ float g_xg[2 * TSEQ * BATCH * G4];     // [dir][T][B][512]
__device__ float g_out1[TSEQ * BATCH * 256];      // layer-1 output [T,B,256]

// ---------------- MUFU-free activations ---------------------------------------
__device__ __forceinline__ float fexp2_fast(float y) {
    float t = y + 12582912.0f;                    // 1.5*2^23 round trick
    int   n = __float_as_int(t) - 0x4B400000;     // round(y)
    float f = y - (t - 12582912.0f);              // f in [-0.5, 0.5]
    float p =             1.3333558146e-3f;
    p = fmaf(p, f, 9.6181291076e-3f);
    p = fmaf(p, f, 5.5504108665e-2f);
    p = fmaf(p, f, 2.4022650696e-1f);
    p = fmaf(p, f, 6.9314718056e-1f);
    p = fmaf(p, f, 1.0f);
    return __int_as_float(__float_as_int(p) + (n << 23));
}
// 1/d via magic init + 2 Newton steps (rel err ~6e-6 — enough here).
__device__ __forceinline__ float frcp_fast(float d) {
    float r = __int_as_float(0x7EF311C3 - __float_as_int(d));
    r = r * (2.0f - d * r);
    r = r * (2.0f - d * r);
    return r;
}
__device__ __forceinline__ float fsig_fast(float x) {
    x = fminf(fmaxf(x, -30.0f), 30.0f);
    float e = fexp2_fast(-1.4426950408889634f * x);   // e^{-x}
    return frcp_fast(1.0f + e);
}
__device__ __forceinline__ float ftanh_fast(float x) {
    x = fminf(fmaxf(x, -15.0f), 15.0f);
    float e = fexp2_fast(-2.8853900817779268f * x);   // e^{-2x}
    return fmaf(2.0f, frcp_fast(1.0f + e), -1.0f);
}

// ---------------- bf16 pair pack/unpack (ALU-pipe only) ------------------------
__device__ __forceinline__ uint32_t pack_bf2(float lo, float hi) {
    uint32_t r;   // d.hi = first operand, d.lo = second
    asm("cvt.rn.bf16x2.f32 %0, %1, %2;" : "=r"(r) : "f"(hi), "f"(lo));
    return r;
}
__device__ __forceinline__ float bflo(uint32_t b) {
    return __int_as_float((int)(b << 16));
}
__device__ __forceinline__ float bfhi(uint32_t b) {
    return __int_as_float((int)(b & 0xFFFF0000u));
}

// ---------------- transpose x: [B,T,128] -> [T,B,128] -------------------------
__global__ void transpose_x(const float4* __restrict__ x, float4* __restrict__ xt) {
    int i = blockIdx.x * blockDim.x + threadIdx.x;   // over T*B*32 float4s
    if (i >= TSEQ * BATCH * 32) return;
    int t  = i >> 11;
    int r  = i & 2047;
    int b  = r >> 5;
    int k4 = r & 31;
    xt[i] = x[((size_t)b * TSEQ + t) * 32 + k4];
}

// ---------------- SGEMM: C[M,N] = A[M,K] * B[N,K]^T + bias1[n] + bias2[n] -----
// (R2 version — at the SIMT fp32 roofline; do not touch.)
#define BM 64
#define BN 64
#define BKK 16
__global__ __launch_bounds__(256) void sgemm_bias(
    const float* __restrict__ A, const float* __restrict__ B,
    const float* __restrict__ bias1, const float* __restrict__ bias2,
    float* __restrict__ C, int M, int N, int K)
{
    __shared__ float As[BKK][BM + 4];
    __shared__ float Bs[BKK][BN + 4];

    int tid = threadIdx.x;
    int tx = tid & 15;
    int ty = tid >> 4;
    int block_m = blockIdx.x * BM;
    int block_n = blockIdx.y * BN;

    int lr = tid >> 2;
    int lc = (tid & 3) * 4;

    const float* Ab = A + (size_t)(block_m + lr) * K + lc;
    const float* Bb = B + (size_t)(block_n + lr) * K + lc;

    float acc[4][4];
#pragma unroll
    for (int i = 0; i < 4; i++)
#pragma unroll
        for (int jj = 0; jj < 4; jj++) acc[i][jj] = 0.f;

    for (int k0 = 0; k0 < K; k0 += BKK) {
        float4 av = *(const float4*)(Ab + k0);
        float4 bv = *(const float4*)(Bb + k0);
        As[lc + 0][lr] = av.x; As[lc + 1][lr] = av.y;
        As[lc + 2][lr] = av.z; As[lc + 3][lr] = av.w;
        Bs[lc + 0][lr] = bv.x; Bs[lc + 1][lr] = bv.y;
        Bs[lc + 2][lr] = bv.z; Bs[lc + 3][lr] = bv.w;
        __syncthreads();
#pragma unroll
        for (int k = 0; k < BKK; k++) {
            float4 a = *(const float4*)&As[k][ty * 4];
            float4 b = *(const float4*)&Bs[k][tx * 4];
            acc[0][0] += a.x * b.x; acc[0][1] += a.x * b.y;
            acc[0][2] += a.x * b.z; acc[0][3] += a.x * b.w;
            acc[1][0] += a.y * b.x; acc[1][1] += a.y * b.y;
            acc[1][2] += a.y * b.z; acc[1][3] += a.y * b.w;
            acc[2][0] += a.z * b.x; acc[2][1] += a.z * b.y;
            acc[2][2] += a.z * b.z; acc[2][3] += a.z * b.w;
            acc[3][0] += a.w * b.x; acc[3][1] += a.w * b.y;
            acc[3][2] += a.w * b.z; acc[3][3] += a.w * b.w;
        }
        __syncthreads();
    }

#pragma unroll
    for (int i = 0; i < 4; i++) {
        size_t row = (size_t)(block_m + ty * 4 + i);
#pragma unroll
        for (int jj = 0; jj < 4; jj++) {
            int n = block_n + tx * 4 + jj;
            C[row * N + n] = acc[i][jj] + __ldg(&bias1[n]) + __ldg(&bias2[n]);
        }
    }
}

// ---------------- recurrent LSTM scan: one CTA per (batch, direction) ---------
// 512 threads; thread j owns gate row j (gate = j>>7 in {i,f,g,o}).
// Whh row j: cols 0..RK-1 fp32 in registers; cols RK..127 bf16 PAIRS in smem
// (uint4 = 8 cols), transposed [q8][j] -> conflict-free LDS.128, half traffic.
#define RK 80
#define SQ8 ((128 - RK) / 8)           // 6 uint4 groups per row
#define REC_SMEM_FLOATS (SQ8 * 4 * G4 + HID + G4)
#define REC_SMEM_BYTES (REC_SMEM_FLOATS * 4)

__global__ __launch_bounds__(512, 1) void lstm_rec(
    const float* __restrict__ xg,        // [dir][T][B][512]
    const float* __restrict__ Whh0,      // fw weights [512][128]
    const float* __restrict__ Whh1,      // bw weights [512][128]
    float* __restrict__ out,             // h output
    int outT, int outB)                  // strides (floats) for t and b
{
    extern __shared__ float sm[];
    uint4* wsu4 = (uint4*)sm;                    // SQ8*512 uint4 (bf16 pairs)
    float* hs = sm + SQ8 * 4 * G4;               // 128 (16B aligned)
    float* gs = hs + HID;                        // 512

    int j   = threadIdx.x;
    int b   = blockIdx.x;
    int dir = blockIdx.y;
    const float* Whh = dir ? Whh1 : Whh0;

    const float4* Wr4 = (const float4*)(Whh + (size_t)j * 128);
    float w[RK];
#pragma unroll
    for (int k4 = 0; k4 < RK / 4; k4++) {
        float4 v = Wr4[k4];
        w[4 * k4 + 0] = v.x; w[4 * k4 + 1] = v.y;
        w[4 * k4 + 2] = v.z; w[4 * k4 + 3] = v.w;
    }
    // cols RK..127 -> bf16 pairs: wsu4[q8*512 + j] covers 8 cols
#pragma unroll
    for (int q8 = 0; q8 < SQ8; q8++) {
        float4 vA = Wr4[RK / 4 + 2 * q8];
        float4 vB = Wr4[RK / 4 + 2 * q8 + 1];
        uint4 pk;
        pk.x = pack_bf2(vA.x, vA.y);
        pk.y = pack_bf2(vA.z, vA.w);
        pk.z = pack_bf2(vB.x, vB.y);
        pk.w = pack_bf2(vB.z, vB.w);
        wsu4[q8 * G4 + j] = pk;
    }

    if (j < HID) hs[j] = 0.f;
    float c = 0.f;
    __syncthreads();

    const float4* hs4 = (const float4*)hs;
    size_t xg_base = (size_t)dir * XGHALF + (size_t)b * G4 + j;
    int t0 = dir ? (TSEQ - 1) : 0;
    float xgv = __ldg(xg + xg_base + (size_t)t0 * (BATCH * G4));
    float* outp = out + dir * HID;
    bool isg = ((j >> 7) == 2);              // tanh gate?

    for (int s = 0; s < TSEQ; s++) {
        int t = dir ? (TSEQ - 1 - s) : s;
        int tn = dir ? max(t - 1, 0) : min(t + 1, TSEQ - 1);
        float xgn = __ldg(xg + xg_base + (size_t)tn * (BATCH * G4));

        float a0 = xgv, a1 = 0.f, a2 = 0.f, a3 = 0.f;
#pragma unroll
        for (int q = 0; q < RK / 4; q++) {       // register half (fp32 exact)
            float4 hv = hs4[q];
            a0 += w[4 * q + 0] * hv.x;
            a1 += w[4 * q + 1] * hv.y;
            a2 += w[4 * q + 2] * hv.z;
            a3 += w[4 * q + 3] * hv.w;
        }
#pragma unroll
        for (int q8 = 0; q8 < SQ8; q8++) {       // smem half (bf16 weights)
            uint4 wb = wsu4[q8 * G4 + j];
            float4 hA = hs4[RK / 4 + 2 * q8];
            float4 hB = hs4[RK / 4 + 2 * q8 + 1];
            a0 += bflo(wb.x) * hA.x;
            a1 += bfhi(wb.x) * hA.y;
            a2 += bflo(wb.y) * hA.z;
            a3 += bfhi(wb.y) * hA.w;
            a0 += bflo(wb.z) * hB.x;
            a1 += bfhi(wb.z) * hB.y;
            a2 += bflo(wb.w) * hB.z;
            a3 += bfhi(wb.w) * hB.w;
        }
        float pre = (a0 + a1) + (a2 + a3);

        // unified MUFU-free activation: tanh(x) = 2*sig(2x)-1
        float xs = isg ? pre + pre : pre;
        float sv = fsig_fast(xs);
        float v  = isg ? fmaf(2.0f, sv, -1.0f) : sv;
        gs[j] = v;
        __syncthreads();

        if (j < HID) {
            float iv = gs[j];
            float fv = gs[j + HID];
            float gv = gs[j + 2 * HID];
            float ov = gs[j + 3 * HID];
            c = fmaf(fv, c, iv * gv);
            float h = ov * ftanh_fast(c);
            hs[j] = h;
            outp[(size_t)t * outT + (size_t)b * outB + j] = h;
        }
        __syncthreads();
        xgv = xgn;
    }
}

// ---------------- launch ------------------------------------------------------
extern "C" void kernel_launch(void* const* d_in, const int* in_sizes, int n_in,
                              void* d_out, int out_size)
{
    const float* x        = (const float*)d_in[0];
    // d_in[1] = lengths (unused, as in the reference)
    const float* Wih_fw1  = (const float*)d_in[2];
    const float* Whh_fw1  = (const float*)d_in[3];
    const float* bih_fw1  = (const float*)d_in[4];
    const float* bhh_fw1  = (const float*)d_in[5];
    const float* Wih_bw1  = (const float*)d_in[6];
    const float* Whh_bw1  = (const float*)d_in[7];
    const float* bih_bw1  = (const float*)d_in[8];
    const float* bhh_bw1  = (const float*)d_in[9];
    const float* Wih_fw2  = (const float*)d_in[10];
    const float* Whh_fw2  = (const float*)d_in[11];
    const float* bih_fw2  = (const float*)d_in[12];
    const float* bhh_fw2  = (const float*)d_in[13];
    const float* Wih_bw2  = (const float*)d_in[14];
    const float* Whh_bw2  = (const float*)d_in[15];
    const float* bih_bw2  = (const float*)d_in[16];
    const float* bhh_bw2  = (const float*)d_in[17];
    float* out = (float*)d_out;

    float *xt, *xg, *out1;
    cudaGetSymbolAddress((void**)&xt,   g_xt);
    cudaGetSymbolAddress((void**)&xg,   g_xg);
    cudaGetSymbolAddress((void**)&out1, g_out1);

    cudaFuncSetAttribute(lstm_rec, cudaFuncAttributeMaxDynamicSharedMemorySize,
                         REC_SMEM_BYTES);

    const int M = TSEQ * BATCH;          // 65536

    // 1) transpose x -> [T,B,128]
    transpose_x<<<(TSEQ * BATCH * 32 + 255) / 256, 256>>>(
        (const float4*)x, (float4*)xt);

    // 2) layer-1 input projections (bias = bih + bhh folded in)
    dim3 gg(M / BM, G4 / BN);
    sgemm_bias<<<gg, 256>>>(xt, Wih_fw1, bih_fw1, bhh_fw1, xg,          M, G4, 128);
    sgemm_bias<<<gg, 256>>>(xt, Wih_bw1, bih_bw1, bhh_bw1, xg + XGHALF, M, G4, 128);

    // 3) layer-1 recurrence -> out1 [T,B,256]
    lstm_rec<<<dim3(BATCH, 2), 512, REC_SMEM_BYTES>>>(
        xg, Whh_fw1, Whh_bw1, out1, BATCH * 256, 256);

    // 4) layer-2 input projections (K = 256)
    sgemm_bias<<<gg, 256>>>(out1, Wih_fw2, bih_fw2, bhh_fw2, xg,          M, G4, 256);
    sgemm_bias<<<gg, 256>>>(out1, Wih_bw2, bih_bw2, bhh_bw2, xg + XGHALF, M, G4, 256);

    // 5) layer-2 recurrence -> d_out [B,T,256]
    lstm_rec<<<dim3(BATCH, 2), 512, REC_SMEM_BYTES>>>(
        xg, Whh_fw2, Whh_bw2, out, 256, TSEQ * 256);
}

// round 8
// speedup vs baseline: 1.5074x; 1.5074x over previous
#include <cuda_runtime.h>
#include <cuda_bf16.h>
#include <cstdint>

// Problem constants
#define TSEQ 1024
#define BATCH 64
#define HID 128
#define G4 512            // 4*HID
#define XGHALF (TSEQ*BATCH*G4)   // per-direction xg elements

// ---------------- scratch (static device globals; no allocations) -------------
__device__ float g_xt[TSEQ * BATCH * 128];        // x transposed to [T,B,128]
__device__ float g_xg[2 * TSEQ * BATCH * G4];     // [dir][T][B][512]
__device__ float g_out1[TSEQ * BATCH * 256];      // layer-1 output [T,B,256]

// ---------------- MUFU-free activations ---------------------------------------
__device__ __forceinline__ float fexp2_fast(float y) {
    float t = y + 12582912.0f;                    // 1.5*2^23 round trick
    int   n = __float_as_int(t) - 0x4B400000;     // round(y)
    float f = y - (t - 12582912.0f);              // f in [-0.5, 0.5]
    float p =             1.3333558146e-3f;
    p = fmaf(p, f, 9.6181291076e-3f);
    p = fmaf(p, f, 5.5504108665e-2f);
    p = fmaf(p, f, 2.4022650696e-1f);
    p = fmaf(p, f, 6.9314718056e-1f);
    p = fmaf(p, f, 1.0f);
    return __int_as_float(__float_as_int(p) + (n << 23));
}
__device__ __forceinline__ float frcp_fast(float d) {
    float r = __int_as_float(0x7EF311C3 - __float_as_int(d));
    r = r * (2.0f - d * r);
    r = r * (2.0f - d * r);
    r = r * (2.0f - d * r);
    return r;
}
__device__ __forceinline__ float fsig_fast(float x) {
    x = fminf(fmaxf(x, -30.0f), 30.0f);
    float e = fexp2_fast(-1.4426950408889634f * x);   // e^{-x}
    return frcp_fast(1.0f + e);
}
__device__ __forceinline__ float ftanh_fast(float x) {
    x = fminf(fmaxf(x, -15.0f), 15.0f);
    float e = fexp2_fast(-2.8853900817779268f * x);   // e^{-2x}
    return fmaf(2.0f, frcp_fast(1.0f + e), -1.0f);
}

// ---------------- bf16 pack/unpack --------------------------------------------
__device__ __forceinline__ uint32_t pack_bf2(float lo, float hi) {
    uint32_t r;   // PTX: cvt.rn.bf16x2.f32 d, a(high), b(low)
    asm("cvt.rn.bf16x2.f32 %0, %1, %2;" : "=r"(r) : "f"(hi), "f"(lo));
    return r;
}
__device__ __forceinline__ float bflo(uint32_t b) {
    return __int_as_float((int)(b << 16));
}
__device__ __forceinline__ float bfhi(uint32_t b) {
    return __int_as_float((int)(b & 0xFFFF0000u));
}

// ---------------- warp-MMA primitives (baseline PTX, sm_80+) -------------------
__device__ __forceinline__ uint32_t smem_u32(const void* p) {
    uint32_t a;
    asm("{ .reg .u64 t; cvta.to.shared.u64 t, %1; cvt.u32.u64 %0, t; }"
        : "=r"(a) : "l"(p));
    return a;
}
__device__ __forceinline__ void ldmx4(uint32_t* r, uint32_t addr) {
    asm volatile("ldmatrix.sync.aligned.m8n8.x4.shared.b16 {%0,%1,%2,%3}, [%4];"
                 : "=r"(r[0]), "=r"(r[1]), "=r"(r[2]), "=r"(r[3]) : "r"(addr));
}
__device__ __forceinline__ void mma16816(float* c, const uint32_t* a,
                                         const uint32_t* b) {
    asm volatile(
        "mma.sync.aligned.m16n8k16.row.col.f32.bf16.bf16.f32 "
        "{%0,%1,%2,%3}, {%4,%5,%6,%7}, {%8,%9}, {%0,%1,%2,%3};"
        : "+f"(c[0]), "+f"(c[1]), "+f"(c[2]), "+f"(c[3])
        : "r"(a[0]), "r"(a[1]), "r"(a[2]), "r"(a[3]), "r"(b[0]), "r"(b[1]));
}
// SW128-style swizzle for 128B-row tiles (row stride 128B = 64 bf16)
__device__ __forceinline__ uint32_t swz(uint32_t off) {
    return off ^ ((off >> 3) & 0x70);
}

// ---------------- transpose x: [B,T,128] -> [T,B,128] -------------------------
__global__ void transpose_x(const float4* __restrict__ x, float4* __restrict__ xt) {
    int i = blockIdx.x * blockDim.x + threadIdx.x;   // over T*B*32 float4s
    if (i >= TSEQ * BATCH * 32) return;
    int t  = i >> 11;
    int r  = i & 2047;
    int b  = r >> 5;
    int k4 = r & 31;
    xt[i] = x[((size_t)b * TSEQ + t) * 32 + k4];
}

// ---------------- tensor-core GEMM (warp mma.sync, bf16 3-pass split) ----------
// C[M,512] = A[M,K]*W[512,K]^T + bias1 + bias2.  Per CTA: 128x128 C-tile,
// 8 warps in 2(m)x4(n), each 64x32 via m16n8k16. K staged 64/iter in smem
// as bf16 hi/lo tiles with SW128 swizzle; ldmatrix.x4 fragment loads.
#define KSTAGE 64
#define TILE_BY (128 * KSTAGE * 2)     // 16384 B per bf16 tile
#define GEMM_SMEM (4 * TILE_BY)        // Ahi, Alo, Bhi, Blo

__global__ __launch_bounds__(256, 1) void gemm_tc(
    const float* __restrict__ A, const float* __restrict__ W,
    const float* __restrict__ bias1, const float* __restrict__ bias2,
    float* __restrict__ C, int K)
{
    extern __shared__ __align__(1024) char smem[];
    uint32_t sAH = smem_u32(smem);
    uint32_t sAL = sAH + TILE_BY;
    uint32_t sBH = sAH + 2 * TILE_BY;
    uint32_t sBL = sAH + 3 * TILE_BY;

    int tid = threadIdx.x;
    int wid = tid >> 5;
    int l   = tid & 31;
    int wm  = wid >> 2;          // 0..1  (64-row slab)
    int wn  = wid & 3;           // 0..3  (32-col slab)
    int bm  = blockIdx.x * 128;
    int bn  = blockIdx.y * 128;

    float acc[4][4][4];
#pragma unroll
    for (int i = 0; i < 4; i++)
#pragma unroll
        for (int jj = 0; jj < 4; jj++)
#pragma unroll
            for (int e = 0; e < 4; e++) acc[i][jj][e] = 0.f;

    // loader mapping: thread t -> row = t>>1, cols (t&1)*32 .. +31 (8 float4)
    int lrow = tid >> 1;
    int lcb  = (tid & 1) * 32;

    // ldmatrix lane address components (within a 128x64 tile)
    int a_row = (l & 7) + ((l >> 3) & 1) * 8;      // + R0
    int a_cb  = ((l >> 4) & 1) * 8;                // + C0
    int b_row = (l & 7) + ((l >> 4) & 1) * 8;      // + N0
    int b_cb  = ((l >> 3) & 1) * 8;                // + C0

    int nst = K / KSTAGE;
    for (int st = 0; st < nst; st++) {
        const float* Ar = A + (size_t)(bm + lrow) * K + st * KSTAGE + lcb;
        const float* Wr = W + (size_t)(bn + lrow) * K + st * KSTAGE + lcb;
        char* smc = smem;
#pragma unroll
        for (int i = 0; i < 8; i++) {
            int c = lcb + i * 4;
            uint32_t ad = swz((uint32_t)(lrow * 128 + c * 2));
            float4 v = *(const float4*)(Ar + i * 4);
            uint32_t h0 = pack_bf2(v.x, v.y), h1 = pack_bf2(v.z, v.w);
            uint32_t l0 = pack_bf2(v.x - bflo(h0), v.y - bfhi(h0));
            uint32_t l1 = pack_bf2(v.z - bflo(h1), v.w - bfhi(h1));
            *(uint2*)(smc + ad)             = make_uint2(h0, h1);
            *(uint2*)(smc + TILE_BY + ad)   = make_uint2(l0, l1);
            float4 u = *(const float4*)(Wr + i * 4);
            uint32_t g0 = pack_bf2(u.x, u.y), g1 = pack_bf2(u.z, u.w);
            uint32_t m0 = pack_bf2(u.x - bflo(g0), u.y - bfhi(g0));
            uint32_t m1 = pack_bf2(u.z - bflo(g1), u.w - bfhi(g1));
            *(uint2*)(smc + 2 * TILE_BY + ad) = make_uint2(g0, g1);
            *(uint2*)(smc + 3 * TILE_BY + ad) = make_uint2(m0, m1);
        }
        __syncthreads();

#pragma unroll
        for (int kk = 0; kk < KSTAGE / 16; kk++) {
            int C0 = kk * 16;
            // B fragments: two ldmatrix.x4 per precision cover 4 n-tiles
            uint32_t bh[8], bl[8];
#pragma unroll
            for (int half = 0; half < 2; half++) {
                uint32_t off = swz((uint32_t)(
                    (wn * 32 + half * 16 + b_row) * 128 + (C0 + b_cb) * 2));
                ldmx4(bh + half * 4, sBH + off);
                ldmx4(bl + half * 4, sBL + off);
            }
            // A fragments + MMA
#pragma unroll
            for (int mt = 0; mt < 4; mt++) {
                uint32_t off = swz((uint32_t)(
                    (wm * 64 + mt * 16 + a_row) * 128 + (C0 + a_cb) * 2));
                uint32_t ah[4], al[4];
                ldmx4(ah, sAH + off);
                ldmx4(al, sAL + off);
#pragma unroll
                for (int nt = 0; nt < 4; nt++) {
                    mma16816(acc[mt][nt], ah, bh + nt * 2);
                    mma16816(acc[mt][nt], al, bh + nt * 2);
                    mma16816(acc[mt][nt], ah, bl + nt * 2);
                }
            }
        }
        __syncthreads();
    }

    // epilogue: bias + store (fragment layout: c0,c1 row=l/4 cols 2(l%4)+{0,1};
    // c2,c3 row+8)
    int crow = l >> 2;
    int ccol = (l & 3) * 2;
#pragma unroll
    for (int nt = 0; nt < 4; nt++) {
        int gc = bn + wn * 32 + nt * 8 + ccol;
        float b0 = __ldg(&bias1[gc])     + __ldg(&bias2[gc]);
        float b1 = __ldg(&bias1[gc + 1]) + __ldg(&bias2[gc + 1]);
#pragma unroll
        for (int mt = 0; mt < 4; mt++) {
            int gr = bm + wm * 64 + mt * 16 + crow;
            float* p0 = C + (size_t)gr * G4 + gc;
            p0[0] = acc[mt][nt][0] + b0;
            p0[1] = acc[mt][nt][1] + b1;
            float* p1 = C + (size_t)(gr + 8) * G4 + gc;
            p1[0] = acc[mt][nt][2] + b0;
            p1[1] = acc[mt][nt][3] + b1;
        }
    }
}

// ---------------- recurrent LSTM scan (R5 form): one CTA per (batch, dir) -----
#define RK 80
#define SKQ ((128 - RK) / 4)           // 12 smem quads per row
#define REC_SMEM_FLOATS ((128 - RK) * G4 + HID + G4)
#define REC_SMEM_BYTES (REC_SMEM_FLOATS * 4)

__global__ __launch_bounds__(512, 1) void lstm_rec(
    const float* __restrict__ xg,        // [dir][T][B][512]
    const float* __restrict__ Whh0,      // fw weights [512][128]
    const float* __restrict__ Whh1,      // bw weights [512][128]
    float* __restrict__ out,             // h output
    int outT, int outB)                  // strides (floats) for t and b
{
    extern __shared__ float sm[];
    float4* ws4 = (float4*)sm;                   // SKQ*512 float4 (cols RK..127)
    float* hs = sm + (128 - RK) * G4;            // 128 (16B aligned)
    float* gs = hs + HID;                        // 512

    int j   = threadIdx.x;
    int b   = blockIdx.x;
    int dir = blockIdx.y;
    const float* Whh = dir ? Whh1 : Whh0;

    const float4* Wr4 = (const float4*)(Whh + (size_t)j * 128);
    float w[RK];
#pragma unroll
    for (int k4 = 0; k4 < RK / 4; k4++) {
        float4 v = Wr4[k4];
        w[4 * k4 + 0] = v.x; w[4 * k4 + 1] = v.y;
        w[4 * k4 + 2] = v.z; w[4 * k4 + 3] = v.w;
    }
#pragma unroll
    for (int q = 0; q < SKQ; q++)
        ws4[q * G4 + j] = Wr4[RK / 4 + q];

    if (j < HID) hs[j] = 0.f;
    float c = 0.f;
    __syncthreads();

    const float4* hs4 = (const float4*)hs;
    size_t xg_base = (size_t)dir * XGHALF + (size_t)b * G4 + j;
    int t0 = dir ? (TSEQ - 1) : 0;
    float xgv = __ldg(xg + xg_base + (size_t)t0 * (BATCH * G4));
    float* outp = out + dir * HID;
    bool isg = ((j >> 7) == 2);              // tanh gate?

    for (int s = 0; s < TSEQ; s++) {
        int t = dir ? (TSEQ - 1 - s) : s;
        int tn = dir ? max(t - 1, 0) : min(t + 1, TSEQ - 1);
        float xgn = __ldg(xg + xg_base + (size_t)tn * (BATCH * G4));

        float a0 = xgv, a1 = 0.f, a2 = 0.f, a3 = 0.f;
#pragma unroll
        for (int q = 0; q < RK / 4; q++) {       // register half
            float4 hv = hs4[q];
            a0 += w[4 * q + 0] * hv.x;
            a1 += w[4 * q + 1] * hv.y;
            a2 += w[4 * q + 2] * hv.z;
            a3 += w[4 * q + 3] * hv.w;
        }
#pragma unroll
        for (int q = 0; q < SKQ; q++) {          // smem half
            float4 hv = hs4[RK / 4 + q];
            float4 wv = ws4[q * G4 + j];
            a0 += wv.x * hv.x;
            a1 += wv.y * hv.y;
            a2 += wv.z * hv.z;
            a3 += wv.w * hv.w;
        }
        float pre = (a0 + a1) + (a2 + a3);

        float xs = isg ? pre + pre : pre;
        float sv = fsig_fast(xs);
        float v  = isg ? fmaf(2.0f, sv, -1.0f) : sv;
        gs[j] = v;
        __syncthreads();

        if (j < HID) {
            float iv = gs[j];
            float fv = gs[j + HID];
            float gv = gs[j + 2 * HID];
            float ov = gs[j + 3 * HID];
            c = fmaf(fv, c, iv * gv);
            float h = ov * ftanh_fast(c);
            hs[j] = h;
            outp[(size_t)t * outT + (size_t)b * outB + j] = h;
        }
        __syncthreads();
        xgv = xgn;
    }
}

// ---------------- launch ------------------------------------------------------
extern "C" void kernel_launch(void* const* d_in, const int* in_sizes, int n_in,
                              void* d_out, int out_size)
{
    const float* x        = (const float*)d_in[0];
    // d_in[1] = lengths (unused, as in the reference)
    const float* Wih_fw1  = (const float*)d_in[2];
    const float* Whh_fw1  = (const float*)d_in[3];
    const float* bih_fw1  = (const float*)d_in[4];
    const float* bhh_fw1  = (const float*)d_in[5];
    const float* Wih_bw1  = (const float*)d_in[6];
    const float* Whh_bw1  = (const float*)d_in[7];
    const float* bih_bw1  = (const float*)d_in[8];
    const float* bhh_bw1  = (const float*)d_in[9];
    const float* Wih_fw2  = (const float*)d_in[10];
    const float* Whh_fw2  = (const float*)d_in[11];
    const float* bih_fw2  = (const float*)d_in[12];
    const float* bhh_fw2  = (const float*)d_in[13];
    const float* Wih_bw2  = (const float*)d_in[14];
    const float* Whh_bw2  = (const float*)d_in[15];
    const float* bih_bw2  = (const float*)d_in[16];
    const float* bhh_bw2  = (const float*)d_in[17];
    float* out = (float*)d_out;

    float *xt, *xg, *out1;
    cudaGetSymbolAddress((void**)&xt,   g_xt);
    cudaGetSymbolAddress((void**)&xg,   g_xg);
    cudaGetSymbolAddress((void**)&out1, g_out1);

    cudaFuncSetAttribute(lstm_rec, cudaFuncAttributeMaxDynamicSharedMemorySize,
                         REC_SMEM_BYTES);
    cudaFuncSetAttribute(gemm_tc, cudaFuncAttributeMaxDynamicSharedMemorySize,
                         GEMM_SMEM);

    const int M = TSEQ * BATCH;          // 65536

    // 1) transpose x -> [T,B,128]
    transpose_x<<<(TSEQ * BATCH * 32 + 255) / 256, 256>>>(
        (const float4*)x, (float4*)xt);

    // 2) layer-1 input projections (tensor cores; bias folded in)
    dim3 gg(M / 128, G4 / 128);
    gemm_tc<<<gg, 256, GEMM_SMEM>>>(xt, Wih_fw1, bih_fw1, bhh_fw1, xg,          128);
    gemm_tc<<<gg, 256, GEMM_SMEM>>>(xt, Wih_bw1, bih_bw1, bhh_bw1, xg + XGHALF, 128);

    // 3) layer-1 recurrence -> out1 [T,B,256]
    lstm_rec<<<dim3(BATCH, 2), 512, REC_SMEM_BYTES>>>(
        xg, Whh_fw1, Whh_bw1, out1, BATCH * 256, 256);

    // 4) layer-2 input projections (K = 256)
    gemm_tc<<<gg, 256, GEMM_SMEM>>>(out1, Wih_fw2, bih_fw2, bhh_fw2, xg,          256);
    gemm_tc<<<gg, 256, GEMM_SMEM>>>(out1, Wih_bw2, bih_bw2, bhh_bw2, xg + XGHALF, 256);

    // 5) layer-2 recurrence -> d_out [B,T,256]
    lstm_rec<<<dim3(BATCH, 2), 512, REC_SMEM_BYTES>>>(
        xg, Whh_fw2, Whh_bw2, out, 256, TSEQ * 256);
}

// round 10
// speedup vs baseline: 1.6189x; 1.0740x over previous
#include <cuda_runtime.h>
#include <cuda_bf16.h>
#include <cstdint>

// Problem constants
#define TSEQ 1024
#define BATCH 64
#define HID 128
#define G4 512            // 4*HID
#define XGHALF (TSEQ*BATCH*G4)   // per-direction xg elements

// ---------------- scratch (static device globals; no allocations) -------------
__device__ float g_xg[2 * TSEQ * BATCH * G4];     // [dir][T][B][512]
__device__ float g_out1[TSEQ * BATCH * 256];      // layer-1 output [T,B,256]
__device__ uint16_t g_ahi[TSEQ * BATCH * 256];    // A hi (bf16), layer 1 or 2
__device__ uint16_t g_alo[TSEQ * BATCH * 256];    // A lo (bf16)
__device__ uint16_t g_whi[512 * 768];             // W hi: fw1|bw1|fw2|bw2
__device__ uint16_t g_wlo[512 * 768];             // W lo

// W offsets (bf16 elements) — fw1:128 cols, bw1:128, fw2:256, bw2:256
#define WOFF_FW1 0
#define WOFF_BW1 (512 * 128)
#define WOFF_FW2 (512 * 256)
#define WOFF_BW2 (512 * 512)

// ---------------- MUFU-free activations ---------------------------------------
__device__ __forceinline__ float fexp2_fast(float y) {
    float t = y + 12582912.0f;                    // 1.5*2^23 round trick
    int   n = __float_as_int(t) - 0x4B400000;     // round(y)
    float f = y - (t - 12582912.0f);              // f in [-0.5, 0.5]
    float p =             1.3333558146e-3f;
    p = fmaf(p, f, 9.6181291076e-3f);
    p = fmaf(p, f, 5.5504108665e-2f);
    p = fmaf(p, f, 2.4022650696e-1f);
    p = fmaf(p, f, 6.9314718056e-1f);
    p = fmaf(p, f, 1.0f);
    return __int_as_float(__float_as_int(p) + (n << 23));
}
__device__ __forceinline__ float frcp_fast(float d) {
    float r = __int_as_float(0x7EF311C3 - __float_as_int(d));
    r = r * (2.0f - d * r);
    r = r * (2.0f - d * r);
    r = r * (2.0f - d * r);
    return r;
}
__device__ __forceinline__ float fsig_fast(float x) {
    x = fminf(fmaxf(x, -30.0f), 30.0f);
    float e = fexp2_fast(-1.4426950408889634f * x);   // e^{-x}
    return frcp_fast(1.0f + e);
}
__device__ __forceinline__ float ftanh_fast(float x) {
    x = fminf(fmaxf(x, -15.0f), 15.0f);
    float e = fexp2_fast(-2.8853900817779268f * x);   // e^{-2x}
    return fmaf(2.0f, frcp_fast(1.0f + e), -1.0f);
}

// ---------------- bf16 pack/unpack --------------------------------------------
__device__ __forceinline__ uint32_t pack_bf2(float lo, float hi) {
    uint32_t r;   // PTX: cvt.rn.bf16x2.f32 d, a(high), b(low)
    asm("cvt.rn.bf16x2.f32 %0, %1, %2;" : "=r"(r) : "f"(hi), "f"(lo));
    return r;
}
__device__ __forceinline__ float bflo(uint32_t b) {
    return __int_as_float((int)(b << 16));
}
__device__ __forceinline__ float bfhi(uint32_t b) {
    return __int_as_float((int)(b & 0xFFFF0000u));
}
__device__ __forceinline__ void split4(float4 v, uint2& hi, uint2& lo) {
    uint32_t h0 = pack_bf2(v.x, v.y), h1 = pack_bf2(v.z, v.w);
    uint32_t l0 = pack_bf2(v.x - bflo(h0), v.y - bfhi(h0));
    uint32_t l1 = pack_bf2(v.z - bflo(h1), v.w - bfhi(h1));
    hi = make_uint2(h0, h1);
    lo = make_uint2(l0, l1);
}

// ---------------- warp-MMA primitives (baseline PTX, sm_80+) -------------------
__device__ __forceinline__ uint32_t smem_u32(const void* p) {
    uint32_t a;
    asm("{ .reg .u64 t; cvta.to.shared.u64 t, %1; cvt.u32.u64 %0, t; }"
        : "=r"(a) : "l"(p));
    return a;
}
__device__ __forceinline__ void ldmx4(uint32_t* r, uint32_t addr) {
    asm volatile("ldmatrix.sync.aligned.m8n8.x4.shared.b16 {%0,%1,%2,%3}, [%4];"
                 : "=r"(r[0]), "=r"(r[1]), "=r"(r[2]), "=r"(r[3]) : "r"(addr));
}
__device__ __forceinline__ void mma16816(float* c, const uint32_t* a,
                                         const uint32_t* b) {
    asm volatile(
        "mma.sync.aligned.m16n8k16.row.col.f32.bf16.bf16.f32 "
        "{%0,%1,%2,%3}, {%4,%5,%6,%7}, {%8,%9}, {%0,%1,%2,%3};"
        : "+f"(c[0]), "+f"(c[1]), "+f"(c[2]), "+f"(c[3])
        : "r"(a[0]), "r"(a[1]), "r"(a[2]), "r"(a[3]), "r"(b[0]), "r"(b[1]));
}
__device__ __forceinline__ void cp16(uint32_t dst, const void* src) {
    asm volatile("cp.async.ca.shared.global [%0], [%1], 16;"
                 :: "r"(dst), "l"(src));
}
#define CP_COMMIT() asm volatile("cp.async.commit_group;" ::: "memory")
#define CP_WAIT0()  asm volatile("cp.async.wait_group 0;" ::: "memory")
// SW128-style swizzle for 128B-row tiles (row stride 128B = 64 bf16)
__device__ __forceinline__ uint32_t swz(uint32_t off) {
    return off ^ ((off >> 3) & 0x70);
}

// ---------------- converters ---------------------------------------------------
// x [B,T,128] -> (transpose to [T,B,128]) hi/lo bf16
__global__ void conv_x(const float4* __restrict__ x,
                       uint2* __restrict__ hi, uint2* __restrict__ lo) {
    int i = blockIdx.x * blockDim.x + threadIdx.x;   // over T*B*32 float4s
    if (i >= TSEQ * BATCH * 32) return;
    int t  = i >> 11;
    int r  = i & 2047;
    int b  = r >> 5;
    int k4 = r & 31;
    float4 v = x[((size_t)b * TSEQ + t) * 32 + k4];
    split4(v, hi[i], lo[i]);
}
// generic fp32 -> bf16 hi/lo split (n4 float4s)
__global__ void conv_split(const float4* __restrict__ src,
                           uint2* __restrict__ hi, uint2* __restrict__ lo,
                           int n4) {
    int i = blockIdx.x * blockDim.x + threadIdx.x;
    if (i >= n4) return;
    split4(src[i], hi[i], lo[i]);
}

// ---------------- tensor-core GEMM (bf16 pre-split, cp.async pipeline) ---------
// C[M,512] = A[M,K]*W[512,K]^T + bias1 + bias2.  Per CTA: 128x128 C-tile,
// 8 warps in 2(m)x4(n), each 64x32 via m16n8k16. K staged 64/iter, double-buffered.
#define KSTAGE 64
#define TILE_BY (128 * KSTAGE * 2)     // 16384 B per bf16 tile
#define STAGE_BY (4 * TILE_BY)         // AH, AL, BH, BL = 64 KB
#define GEMM_SMEM (2 * STAGE_BY)       // double buffer = 128 KB

__global__ __launch_bounds__(256, 1) void gemm_tc(
    const uint16_t* __restrict__ Ahi, const uint16_t* __restrict__ Alo,
    const uint16_t* __restrict__ Whi, const uint16_t* __restrict__ Wlo,
    const float* __restrict__ bias1, const float* __restrict__ bias2,
    float* __restrict__ C, int K)
{
    extern __shared__ __align__(1024) char smem[];
    uint32_t sb = smem_u32(smem);

    int tid = threadIdx.x;
    int wid = tid >> 5;
    int l   = tid & 31;
    int wm  = wid >> 2;          // 0..1  (64-row slab)
    int wn  = wid & 3;           // 0..3  (32-col slab)
    int bm  = blockIdx.x * 128;
    int bn  = blockIdx.y * 128;

    float acc[4][4][4];
#pragma unroll
    for (int i = 0; i < 4; i++)
#pragma unroll
        for (int jj = 0; jj < 4; jj++)
#pragma unroll
            for (int e = 0; e < 4; e++) acc[i][jj][e] = 0.f;

    // loader: thread -> row tid>>1, four 16B chunks at col-chunks (tid&1)*4+q
    int lrow = tid >> 1;
    const uint16_t* Arow_h = Ahi + (size_t)(bm + lrow) * K;
    const uint16_t* Arow_l = Alo + (size_t)(bm + lrow) * K;
    const uint16_t* Wrow_h = Whi + (size_t)(bn + lrow) * K;
    const uint16_t* Wrow_l = Wlo + (size_t)(bn + lrow) * K;

    // ldmatrix lane address components (within a 128x64 tile)
    int a_row = (l & 7) + ((l >> 3) & 1) * 8;
    int a_cb  = ((l >> 4) & 1) * 8;
    int b_row = (l & 7) + ((l >> 4) & 1) * 8;
    int b_cb  = ((l >> 3) & 1) * 8;

    int nst = K / KSTAGE;

    // --- stage loader (cp.async, 16 chunks per thread) ---
#define LOAD_STAGE(st, buf)                                                   \
    do {                                                                      \
        uint32_t base_ = sb + (buf) * STAGE_BY;                               \
        int k0_ = (st) * KSTAGE;                                              \
        _Pragma("unroll")                                                     \
        for (int q_ = 0; q_ < 4; q_++) {                                      \
            int c8_ = (tid & 1) * 4 + q_;                                     \
            uint32_t d_ = swz((uint32_t)(lrow * 128 + c8_ * 16));             \
            int so_ = k0_ + c8_ * 8;                                          \
            cp16(base_ + 0 * TILE_BY + d_, Arow_h + so_);                     \
            cp16(base_ + 1 * TILE_BY + d_, Arow_l + so_);                     \
            cp16(base_ + 2 * TILE_BY + d_, Wrow_h + so_);                     \
            cp16(base_ + 3 * TILE_BY + d_, Wrow_l + so_);                     \
        }                                                                     \
        CP_COMMIT();                                                          \
    } while (0)

    LOAD_STAGE(0, 0);

    for (int st = 0; st < nst; st++) {
        int buf = st & 1;
        CP_WAIT0();
        __syncthreads();
        if (st + 1 < nst) LOAD_STAGE(st + 1, buf ^ 1);

        uint32_t sAH = sb + buf * STAGE_BY;
        uint32_t sAL = sAH + TILE_BY;
        uint32_t sBH = sAH + 2 * TILE_BY;
        uint32_t sBL = sAH + 3 * TILE_BY;

#pragma unroll
        for (int kk = 0; kk < KSTAGE / 16; kk++) {
            int C0 = kk * 16;
            uint32_t bh[8], bl[8];
#pragma unroll
            for (int half = 0; half < 2; half++) {
                uint32_t off = swz((uint32_t)(
                    (wn * 32 + half * 16 + b_row) * 128 + (C0 + b_cb) * 2));
                ldmx4(bh + half * 4, sBH + off);
                ldmx4(bl + half * 4, sBL + off);
            }
#pragma unroll
            for (int mt = 0; mt < 4; mt++) {
                uint32_t off = swz((uint32_t)(
                    (wm * 64 + mt * 16 + a_row) * 128 + (C0 + a_cb) * 2));
                uint32_t ah[4], al[4];
                ldmx4(ah, sAH + off);
                ldmx4(al, sAL + off);
#pragma unroll
                for (int nt = 0; nt < 4; nt++) {
                    mma16816(acc[mt][nt], ah, bh + nt * 2);
                    mma16816(acc[mt][nt], al, bh + nt * 2);
                    mma16816(acc[mt][nt], ah, bl + nt * 2);
                }
            }
        }
        __syncthreads();
    }

    // epilogue: bias + store
    int crow = l >> 2;
    int ccol = (l & 3) * 2;
#pragma unroll
    for (int nt = 0; nt < 4; nt++) {
        int gc = bn + wn * 32 + nt * 8 + ccol;
        float b0 = __ldg(&bias1[gc])     + __ldg(&bias2[gc]);
        float b1 = __ldg(&bias1[gc + 1]) + __ldg(&bias2[gc + 1]);
#pragma unroll
        for (int mt = 0; mt < 4; mt++) {
            int gr = bm + wm * 64 + mt * 16 + crow;
            float* p0 = C + (size_t)gr * G4 + gc;
            p0[0] = acc[mt][nt][0] + b0;
            p0[1] = acc[mt][nt][1] + b1;
            float* p1 = C + (size_t)(gr + 8) * G4 + gc;
            p1[0] = acc[mt][nt][2] + b0;
            p1[1] = acc[mt][nt][3] + b1;
        }
    }
}

// ---------------- recurrent LSTM scan (R5 form): one CTA per (batch, dir) -----
#define RK 80
#define SKQ ((128 - RK) / 4)           // 12 smem quads per row
#define REC_SMEM_FLOATS ((128 - RK) * G4 + HID + G4)
#define REC_SMEM_BYTES (REC_SMEM_FLOATS * 4)

__global__ __launch_bounds__(512, 1) void lstm_rec(
    const float* __restrict__ xg,        // [dir][T][B][512]
    const float* __restrict__ Whh0,      // fw weights [512][128]
    const float* __restrict__ Whh1,      // bw weights [512][128]
    float* __restrict__ out,             // h output
    int outT, int outB)                  // strides (floats) for t and b
{
    extern __shared__ float sm[];
    float4* ws4 = (float4*)sm;                   // SKQ*512 float4 (cols RK..127)
    float* hs = sm + (128 - RK) * G4;            // 128 (16B aligned)
    float* gs = hs + HID;                        // 512

    int j   = threadIdx.x;
    int b   = blockIdx.x;
    int dir = blockIdx.y;
    const float* Whh = dir ? Whh1 : Whh0;

    const float4* Wr4 = (const float4*)(Whh + (size_t)j * 128);
    float w[RK];
#pragma unroll
    for (int k4 = 0; k4 < RK / 4; k4++) {
        float4 v = Wr4[k4];
        w[4 * k4 + 0] = v.x; w[4 * k4 + 1] = v.y;
        w[4 * k4 + 2] = v.z; w[4 * k4 + 3] = v.w;
    }
#pragma unroll
    for (int q = 0; q < SKQ; q++)
        ws4[q * G4 + j] = Wr4[RK / 4 + q];

    if (j < HID) hs[j] = 0.f;
    float c = 0.f;
    __syncthreads();

    const float4* hs4 = (const float4*)hs;
    size_t xg_base = (size_t)dir * XGHALF + (size_t)b * G4 + j;
    int t0 = dir ? (TSEQ - 1) : 0;
    float xgv = __ldg(xg + xg_base + (size_t)t0 * (BATCH * G4));
    float* outp = out + dir * HID;
    bool isg = ((j >> 7) == 2);              // tanh gate?

    for (int s = 0; s < TSEQ; s++) {
        int t = dir ? (TSEQ - 1 - s) : s;
        int tn = dir ? max(t - 1, 0) : min(t + 1, TSEQ - 1);
        float xgn = __ldg(xg + xg_base + (size_t)tn * (BATCH * G4));

        float a0 = xgv, a1 = 0.f, a2 = 0.f, a3 = 0.f;
#pragma unroll
        for (int q = 0; q < RK / 4; q++) {       // register half
            float4 hv = hs4[q];
            a0 += w[4 * q + 0] * hv.x;
            a1 += w[4 * q + 1] * hv.y;
            a2 += w[4 * q + 2] * hv.z;
            a3 += w[4 * q + 3] * hv.w;
        }
#pragma unroll
        for (int q = 0; q < SKQ; q++) {          // smem half
            float4 hv = hs4[RK / 4 + q];
            float4 wv = ws4[q * G4 + j];
            a0 += wv.x * hv.x;
            a1 += wv.y * hv.y;
            a2 += wv.z * hv.z;
            a3 += wv.w * hv.w;
        }
        float pre = (a0 + a1) + (a2 + a3);

        float xs = isg ? pre + pre : pre;
        float sv = fsig_fast(xs);
        float v  = isg ? fmaf(2.0f, sv, -1.0f) : sv;
        gs[j] = v;
        __syncthreads();

        if (j < HID) {
            float iv = gs[j];
            float fv = gs[j + HID];
            float gv = gs[j + 2 * HID];
            float ov = gs[j + 3 * HID];
            c = fmaf(fv, c, iv * gv);
            float h = ov * ftanh_fast(c);
            hs[j] = h;
            outp[(size_t)t * outT + (size_t)b * outB + j] = h;
        }
        __syncthreads();
        xgv = xgn;
    }
}

// ---------------- launch ------------------------------------------------------
extern "C" void kernel_launch(void* const* d_in, const int* in_sizes, int n_in,
                              void* d_out, int out_size)
{
    const float* x        = (const float*)d_in[0];
    // d_in[1] = lengths (unused, as in the reference)
    const float* Wih_fw1  = (const float*)d_in[2];
    const float* Whh_fw1  = (const float*)d_in[3];
    const float* bih_fw1  = (const float*)d_in[4];
    const float* bhh_fw1  = (const float*)d_in[5];
    const float* Wih_bw1  = (const float*)d_in[6];
    const float* Whh_bw1  = (const float*)d_in[7];
    const float* bih_bw1  = (const float*)d_in[8];
    const float* bhh_bw1  = (const float*)d_in[9];
    const float* Wih_fw2  = (const float*)d_in[10];
    const float* Whh_fw2  = (const float*)d_in[11];
    const float* bih_fw2  = (const float*)d_in[12];
    const float* bhh_fw2  = (const float*)d_in[13];
    const float* Wih_bw2  = (const float*)d_in[14];
    const float* Whh_bw2  = (const float*)d_in[15];
    const float* bih_bw2  = (const float*)d_in[16];
    const float* bhh_bw2  = (const float*)d_in[17];
    float* out = (float*)d_out;

    float *xg, *out1;
    uint16_t *ahi, *alo, *whi, *wlo;
    cudaGetSymbolAddress((void**)&xg,   g_xg);
    cudaGetSymbolAddress((void**)&out1, g_out1);
    cudaGetSymbolAddress((void**)&ahi,  g_ahi);
    cudaGetSymbolAddress((void**)&alo,  g_alo);
    cudaGetSymbolAddress((void**)&whi,  g_whi);
    cudaGetSymbolAddress((void**)&wlo,  g_wlo);

    cudaFuncSetAttribute(lstm_rec, cudaFuncAttributeMaxDynamicSharedMemorySize,
                         REC_SMEM_BYTES);
    cudaFuncSetAttribute(gemm_tc, cudaFuncAttributeMaxDynamicSharedMemorySize,
                         GEMM_SMEM);

    const int M = TSEQ * BATCH;          // 65536

    // 0) one-time weight splits (tiny)
    conv_split<<<(512 * 128 / 4 + 255) / 256, 256>>>(
        (const float4*)Wih_fw1, (uint2*)(whi + WOFF_FW1), (uint2*)(wlo + WOFF_FW1), 512 * 128 / 4);
    conv_split<<<(512 * 128 / 4 + 255) / 256, 256>>>(
        (const float4*)Wih_bw1, (uint2*)(whi + WOFF_BW1), (uint2*)(wlo + WOFF_BW1), 512 * 128 / 4);
    conv_split<<<(512 * 256 / 4 + 255) / 256, 256>>>(
        (const float4*)Wih_fw2, (uint2*)(whi + WOFF_FW2), (uint2*)(wlo + WOFF_FW2), 512 * 256 / 4);
    conv_split<<<(512 * 256 / 4 + 255) / 256, 256>>>(
        (const float4*)Wih_bw2, (uint2*)(whi + WOFF_BW2), (uint2*)(wlo + WOFF_BW2), 512 * 256 / 4);

    // 1) x: transpose + split -> Ahi/Alo [T*B, 128]
    conv_x<<<(TSEQ * BATCH * 32 + 255) / 256, 256>>>(
        (const float4*)x, (uint2*)ahi, (uint2*)alo);

    // 2) layer-1 input projections (tensor cores; bias folded in)
    dim3 gg(M / 128, G4 / 128);
    gemm_tc<<<gg, 256, GEMM_SMEM>>>(ahi, alo, whi + WOFF_FW1, wlo + WOFF_FW1,
                                    bih_fw1, bhh_fw1, xg,          128);
    gemm_tc<<<gg, 256, GEMM_SMEM>>>(ahi, alo, whi + WOFF_BW1, wlo + WOFF_BW1,
                                    bih_bw1, bhh_bw1, xg + XGHALF, 128);

    // 3) layer-1 recurrence -> out1 [T,B,256]
    lstm_rec<<<dim3(BATCH, 2), 512, REC_SMEM_BYTES>>>(
        xg, Whh_fw1, Whh_bw1, out1, BATCH * 256, 256);

    // 4) split out1 -> Ahi/Alo [T*B, 256]
    conv_split<<<(M * 256 / 4 + 255) / 256, 256>>>(
        (const float4*)out1, (uint2*)ahi, (uint2*)alo, M * 256 / 4);

    // 5) layer-2 input projections (K = 256)
    gemm_tc<<<gg, 256, GEMM_SMEM>>>(ahi, alo, whi + WOFF_FW2, wlo + WOFF_FW2,
                                    bih_fw2, bhh_fw2, xg,          256);
    gemm_tc<<<gg, 256, GEMM_SMEM>>>(ahi, alo, whi + WOFF_BW2, wlo + WOFF_BW2,
                                    bih_bw2, bhh_bw2, xg + XGHALF, 256);

    // 6) layer-2 recurrence -> d_out [B,T,256]
    lstm_rec<<<dim3(BATCH, 2), 512, REC_SMEM_BYTES>>>(
        xg, Whh_fw2, Whh_bw2, out, 256, TSEQ * 256);
}

// round 11
// speedup vs baseline: 1.7974x; 1.1103x over previous
#include <cuda_runtime.h>
#include <cuda_bf16.h>
#include <cstdint>

// Problem constants
#define TSEQ 1024
#define BATCH 64
#define HID 128
#define G4 512            // 4*HID
#define XGHALF (TSEQ*BATCH*G4)   // per-direction xg elements

// ---------------- scratch (static device globals; no allocations) -------------
__device__ float g_xg[2 * TSEQ * BATCH * G4];     // [dir][T][B][512]
__device__ uint16_t g_ahi[TSEQ * BATCH * 256];    // A hi (bf16), layer 1 or 2
__device__ uint16_t g_alo[TSEQ * BATCH * 256];    // A lo (bf16)
__device__ uint16_t g_whi[512 * 768];             // W hi: fw1|bw1|fw2|bw2
__device__ uint16_t g_wlo[512 * 768];             // W lo

// W offsets (bf16 elements) — fw1:128 cols, bw1:128, fw2:256, bw2:256
#define WOFF_FW1 0
#define WOFF_BW1 (512 * 128)
#define WOFF_FW2 (512 * 256)
#define WOFF_BW2 (512 * 512)

// ---------------- MUFU-free activations ---------------------------------------
__device__ __forceinline__ float fexp2_fast(float y) {
    float t = y + 12582912.0f;                    // 1.5*2^23 round trick
    int   n = __float_as_int(t) - 0x4B400000;     // round(y)
    float f = y - (t - 12582912.0f);              // f in [-0.5, 0.5]
    float p =             1.3333558146e-3f;
    p = fmaf(p, f, 9.6181291076e-3f);
    p = fmaf(p, f, 5.5504108665e-2f);
    p = fmaf(p, f, 2.4022650696e-1f);
    p = fmaf(p, f, 6.9314718056e-1f);
    p = fmaf(p, f, 1.0f);
    return __int_as_float(__float_as_int(p) + (n << 23));
}
__device__ __forceinline__ float frcp_fast(float d) {
    float r = __int_as_float(0x7EF311C3 - __float_as_int(d));
    r = r * (2.0f - d * r);
    r = r * (2.0f - d * r);
    r = r * (2.0f - d * r);
    return r;
}
__device__ __forceinline__ float fsig_fast(float x) {
    x = fminf(fmaxf(x, -30.0f), 30.0f);
    float e = fexp2_fast(-1.4426950408889634f * x);   // e^{-x}
    return frcp_fast(1.0f + e);
}
__device__ __forceinline__ float ftanh_fast(float x) {
    x = fminf(fmaxf(x, -15.0f), 15.0f);
    float e = fexp2_fast(-2.8853900817779268f * x);   // e^{-2x}
    return fmaf(2.0f, frcp_fast(1.0f + e), -1.0f);
}

// ---------------- bf16 pack/unpack --------------------------------------------
__device__ __forceinline__ uint32_t pack_bf2(float lo, float hi) {
    uint32_t r;   // PTX: cvt.rn.bf16x2.f32 d, a(high), b(low)
    asm("cvt.rn.bf16x2.f32 %0, %1, %2;" : "=r"(r) : "f"(hi), "f"(lo));
    return r;
}
__device__ __forceinline__ float bflo(uint32_t b) {
    return __int_as_float((int)(b << 16));
}
__device__ __forceinline__ float bfhi(uint32_t b) {
    return __int_as_float((int)(b & 0xFFFF0000u));
}
__device__ __forceinline__ void split4(float4 v, uint2& hi, uint2& lo) {
    uint32_t h0 = pack_bf2(v.x, v.y), h1 = pack_bf2(v.z, v.w);
    uint32_t l0 = pack_bf2(v.x - bflo(h0), v.y - bfhi(h0));
    uint32_t l1 = pack_bf2(v.z - bflo(h1), v.w - bfhi(h1));
    hi = make_uint2(h0, h1);
    lo = make_uint2(l0, l1);
}

// ---------------- warp-MMA primitives (baseline PTX, sm_80+) -------------------
__device__ __forceinline__ uint32_t smem_u32(const void* p) {
    uint32_t a;
    asm("{ .reg .u64 t; cvta.to.shared.u64 t, %1; cvt.u32.u64 %0, t; }"
        : "=r"(a) : "l"(p));
    return a;
}
__device__ __forceinline__ void ldmx4(uint32_t* r, uint32_t addr) {
    asm volatile("ldmatrix.sync.aligned.m8n8.x4.shared.b16 {%0,%1,%2,%3}, [%4];"
                 : "=r"(r[0]), "=r"(r[1]), "=r"(r[2]), "=r"(r[3]) : "r"(addr));
}
__device__ __forceinline__ void mma16816(float* c, const uint32_t* a,
                                         const uint32_t* b) {
    asm volatile(
        "mma.sync.aligned.m16n8k16.row.col.f32.bf16.bf16.f32 "
        "{%0,%1,%2,%3}, {%4,%5,%6,%7}, {%8,%9}, {%0,%1,%2,%3};"
        : "+f"(c[0]), "+f"(c[1]), "+f"(c[2]), "+f"(c[3])
        : "r"(a[0]), "r"(a[1]), "r"(a[2]), "r"(a[3]), "r"(b[0]), "r"(b[1]));
}
__device__ __forceinline__ void cp16(uint32_t dst, const void* src) {
    asm volatile("cp.async.ca.shared.global [%0], [%1], 16;"
                 :: "r"(dst), "l"(src));
}
#define CP_COMMIT() asm volatile("cp.async.commit_group;" ::: "memory")
#define CP_WAIT0()  asm volatile("cp.async.wait_group 0;" ::: "memory")
// SW128-style swizzle for 128B-row tiles (row stride 128B = 64 bf16)
__device__ __forceinline__ uint32_t swz(uint32_t off) {
    return off ^ ((off >> 3) & 0x70);
}

// ---------------- converters ---------------------------------------------------
// x [B,T,128] -> (transpose to [T,B,128]) hi/lo bf16
__global__ void conv_x(const float4* __restrict__ x,
                       uint2* __restrict__ hi, uint2* __restrict__ lo) {
    int i = blockIdx.x * blockDim.x + threadIdx.x;   // over T*B*32 float4s
    if (i >= TSEQ * BATCH * 32) return;
    int t  = i >> 11;
    int r  = i & 2047;
    int b  = r >> 5;
    int k4 = r & 31;
    float4 v = x[((size_t)b * TSEQ + t) * 32 + k4];
    split4(v, hi[i], lo[i]);
}
// generic fp32 -> bf16 hi/lo split (n4 float4s)
__global__ void conv_split(const float4* __restrict__ src,
                           uint2* __restrict__ hi, uint2* __restrict__ lo,
                           int n4) {
    int i = blockIdx.x * blockDim.x + threadIdx.x;
    if (i >= n4) return;
    split4(src[i], hi[i], lo[i]);
}

// ---------------- tensor-core GEMM (bf16 pre-split, cp.async pipeline) ---------
// C[M,512] = A[M,K]*W[512,K]^T + bias1 + bias2.  Per CTA: 128x128 C-tile,
// 8 warps in 2(m)x4(n), each 64x32 via m16n8k16. K staged 64/iter, double-buffered.
#define KSTAGE 64
#define TILE_BY (128 * KSTAGE * 2)     // 16384 B per bf16 tile
#define STAGE_BY (4 * TILE_BY)         // AH, AL, BH, BL = 64 KB
#define GEMM_SMEM (2 * STAGE_BY)       // double buffer = 128 KB

__global__ __launch_bounds__(256, 1) void gemm_tc(
    const uint16_t* __restrict__ Ahi, const uint16_t* __restrict__ Alo,
    const uint16_t* __restrict__ Whi, const uint16_t* __restrict__ Wlo,
    const float* __restrict__ bias1, const float* __restrict__ bias2,
    float* __restrict__ C, int K)
{
    extern __shared__ __align__(1024) char smem[];
    uint32_t sb = smem_u32(smem);

    int tid = threadIdx.x;
    int wid = tid >> 5;
    int l   = tid & 31;
    int wm  = wid >> 2;          // 0..1  (64-row slab)
    int wn  = wid & 3;           // 0..3  (32-col slab)
    int bm  = blockIdx.x * 128;
    int bn  = blockIdx.y * 128;

    float acc[4][4][4];
#pragma unroll
    for (int i = 0; i < 4; i++)
#pragma unroll
        for (int jj = 0; jj < 4; jj++)
#pragma unroll
            for (int e = 0; e < 4; e++) acc[i][jj][e] = 0.f;

    // loader: thread -> row tid>>1, four 16B chunks at col-chunks (tid&1)*4+q
    int lrow = tid >> 1;
    const uint16_t* Arow_h = Ahi + (size_t)(bm + lrow) * K;
    const uint16_t* Arow_l = Alo + (size_t)(bm + lrow) * K;
    const uint16_t* Wrow_h = Whi + (size_t)(bn + lrow) * K;
    const uint16_t* Wrow_l = Wlo + (size_t)(bn + lrow) * K;

    // ldmatrix lane address components (within a 128x64 tile)
    int a_row = (l & 7) + ((l >> 3) & 1) * 8;
    int a_cb  = ((l >> 4) & 1) * 8;
    int b_row = (l & 7) + ((l >> 4) & 1) * 8;
    int b_cb  = ((l >> 3) & 1) * 8;

    int nst = K / KSTAGE;

    // --- stage loader (cp.async, 16 chunks per thread) ---
#define LOAD_STAGE(st, buf)                                                   \
    do {                                                                      \
        uint32_t base_ = sb + (buf) * STAGE_BY;                               \
        int k0_ = (st) * KSTAGE;                                              \
        _Pragma("unroll")                                                     \
        for (int q_ = 0; q_ < 4; q_++) {                                      \
            int c8_ = (tid & 1) * 4 + q_;                                     \
            uint32_t d_ = swz((uint32_t)(lrow * 128 + c8_ * 16));             \
            int so_ = k0_ + c8_ * 8;                                          \
            cp16(base_ + 0 * TILE_BY + d_, Arow_h + so_);                     \
            cp16(base_ + 1 * TILE_BY + d_, Arow_l + so_);                     \
            cp16(base_ + 2 * TILE_BY + d_, Wrow_h + so_);                     \
            cp16(base_ + 3 * TILE_BY + d_, Wrow_l + so_);                     \
        }                                                                     \
        CP_COMMIT();                                                          \
    } while (0)

    LOAD_STAGE(0, 0);

    for (int st = 0; st < nst; st++) {
        int buf = st & 1;
        CP_WAIT0();
        __syncthreads();
        if (st + 1 < nst) LOAD_STAGE(st + 1, buf ^ 1);

        uint32_t sAH = sb + buf * STAGE_BY;
        uint32_t sAL = sAH + TILE_BY;
        uint32_t sBH = sAH + 2 * TILE_BY;
        uint32_t sBL = sAH + 3 * TILE_BY;

#pragma unroll
        for (int kk = 0; kk < KSTAGE / 16; kk++) {
            int C0 = kk * 16;
            uint32_t bh[8], bl[8];
#pragma unroll
            for (int half = 0; half < 2; half++) {
                uint32_t off = swz((uint32_t)(
                    (wn * 32 + half * 16 + b_row) * 128 + (C0 + b_cb) * 2));
                ldmx4(bh + half * 4, sBH + off);
                ldmx4(bl + half * 4, sBL + off);
            }
#pragma unroll
            for (int mt = 0; mt < 4; mt++) {
                uint32_t off = swz((uint32_t)(
                    (wm * 64 + mt * 16 + a_row) * 128 + (C0 + a_cb) * 2));
                uint32_t ah[4], al[4];
                ldmx4(ah, sAH + off);
                ldmx4(al, sAL + off);
#pragma unroll
                for (int nt = 0; nt < 4; nt++) {
                    mma16816(acc[mt][nt], ah, bh + nt * 2);
                    mma16816(acc[mt][nt], al, bh + nt * 2);
                    mma16816(acc[mt][nt], ah, bl + nt * 2);
                }
            }
        }
        __syncthreads();
    }

    // epilogue: bias + store
    int crow = l >> 2;
    int ccol = (l & 3) * 2;
#pragma unroll
    for (int nt = 0; nt < 4; nt++) {
        int gc = bn + wn * 32 + nt * 8 + ccol;
        float b0 = __ldg(&bias1[gc])     + __ldg(&bias2[gc]);
        float b1 = __ldg(&bias1[gc + 1]) + __ldg(&bias2[gc + 1]);
#pragma unroll
        for (int mt = 0; mt < 4; mt++) {
            int gr = bm + wm * 64 + mt * 16 + crow;
            float* p0 = C + (size_t)gr * G4 + gc;
            p0[0] = acc[mt][nt][0] + b0;
            p0[1] = acc[mt][nt][1] + b1;
            float* p1 = C + (size_t)(gr + 8) * G4 + gc;
            p1[0] = acc[mt][nt][2] + b0;
            p1[1] = acc[mt][nt][3] + b1;
        }
    }
}

// ---------------- recurrent LSTM scan: 256 threads, 2 gate-rows per thread -----
// Thread tid owns rows tid and tid+256:
//   tid<128:   row tid   = gate i (sigmoid),  row tid+256 = gate g (tanh)
//   tid>=128:  row tid   = gate f (sigmoid),  row tid+256 = gate o (sigmoid)
// So thread tid<128 keeps i,g in registers; f,o cross via smem. h quads are
// loaded ONCE per thread and feed both rows (halves the broadcast traffic).
#define RK2 80
#define SKQ2 ((128 - RK2) / 4)          // 12 smem quads per row
#define REC2_SMEM (SKQ2 * G4 * 16 + (HID + 2 * HID) * 4)

__global__ __launch_bounds__(256, 1) void lstm_rec2(
    const float* __restrict__ xg,        // [dir][T][B][512]
    const float* __restrict__ Whh0,      // fw weights [512][128]
    const float* __restrict__ Whh1,      // bw weights [512][128]
    float* __restrict__ out,             // fp32 h output (layer 2) or unused
    int outT, int outB,                  // strides (floats) for t and b
    uint16_t* __restrict__ shi,          // if non-null: write bf16 hi/lo split
    uint16_t* __restrict__ slo)          //   at [t][b][dir*128+j] (layer 1)
{
    extern __shared__ float sm[];
    float4* ws4 = (float4*)sm;                   // SKQ2*512 quads: [q][row]
    float* hs  = sm + SKQ2 * 4 * G4;             // 128 (16B aligned)
    float* gsF = hs + HID;                       // 128 (f gate)
    float* gsO = gsF + HID;                      // 128 (o gate)

    int tid = threadIdx.x;
    int b   = blockIdx.x;
    int dir = blockIdx.y;
    const float* Whh = dir ? Whh1 : Whh0;
    int r0 = tid, r1 = tid + 256;

    const float4* W0 = (const float4*)(Whh + (size_t)r0 * 128);
    const float4* W1 = (const float4*)(Whh + (size_t)r1 * 128);
    float w0[RK2], w1[RK2];
#pragma unroll
    for (int q = 0; q < RK2 / 4; q++) {
        float4 v = W0[q];
        w0[4 * q + 0] = v.x; w0[4 * q + 1] = v.y;
        w0[4 * q + 2] = v.z; w0[4 * q + 3] = v.w;
        v = W1[q];
        w1[4 * q + 0] = v.x; w1[4 * q + 1] = v.y;
        w1[4 * q + 2] = v.z; w1[4 * q + 3] = v.w;
    }
#pragma unroll
    for (int q = RK2 / 4; q < 32; q++) {
        ws4[(q - RK2 / 4) * G4 + r0] = W0[q];
        ws4[(q - RK2 / 4) * G4 + r1] = W1[q];
    }

    if (tid < HID) hs[tid] = 0.f;
    float c = 0.f;
    __syncthreads();

    const float4* hs4 = (const float4*)hs;
    size_t xgb0 = (size_t)dir * XGHALF + (size_t)b * G4 + r0;
    size_t xgb1 = xgb0 + 256;
    int t0 = dir ? (TSEQ - 1) : 0;
    float xg0 = __ldg(xg + xgb0 + (size_t)t0 * (BATCH * G4));
    float xg1 = __ldg(xg + xgb1 + (size_t)t0 * (BATCH * G4));
    bool lohalf = (tid < HID);

    for (int s = 0; s < TSEQ; s++) {
        int t = dir ? (TSEQ - 1 - s) : s;
        int tn = dir ? max(t - 1, 0) : min(t + 1, TSEQ - 1);
        float xg0n = __ldg(xg + xgb0 + (size_t)tn * (BATCH * G4));
        float xg1n = __ldg(xg + xgb1 + (size_t)tn * (BATCH * G4));

        float a0 = xg0, a1 = 0.f, a2 = 0.f, a3 = 0.f;
        float b0 = xg1, b1 = 0.f, b2 = 0.f, b3 = 0.f;
#pragma unroll
        for (int q = 0; q < RK2 / 4; q++) {      // register half, both rows
            float4 hv = hs4[q];
            a0 += w0[4 * q + 0] * hv.x;
            a1 += w0[4 * q + 1] * hv.y;
            a2 += w0[4 * q + 2] * hv.z;
            a3 += w0[4 * q + 3] * hv.w;
            b0 += w1[4 * q + 0] * hv.x;
            b1 += w1[4 * q + 1] * hv.y;
            b2 += w1[4 * q + 2] * hv.z;
            b3 += w1[4 * q + 3] * hv.w;
        }
#pragma unroll
        for (int q = 0; q < SKQ2; q++) {         // smem half, both rows
            float4 hv = hs4[RK2 / 4 + q];
            float4 u = ws4[q * G4 + r0];
            float4 v = ws4[q * G4 + r1];
            a0 += u.x * hv.x; a1 += u.y * hv.y;
            a2 += u.z * hv.z; a3 += u.w * hv.w;
            b0 += v.x * hv.x; b1 += v.y * hv.y;
            b2 += v.z * hv.z; b3 += v.w * hv.w;
        }
        float pre0 = (a0 + a1) + (a2 + a3);      // gate i (tid<128) / f
        float pre1 = (b0 + b1) + (b2 + b3);      // gate g (tid<128) / o

        float v0 = fsig_fast(pre0);
        float v1, iv = 0.f, gv = 0.f;
        if (lohalf) {
            v1 = ftanh_fast(pre1);               // g
            iv = v0; gv = v1;
        } else {
            v1 = fsig_fast(pre1);                // o
            gsF[tid - HID] = v0;
            gsO[tid - HID] = v1;
        }
        __syncthreads();

        if (lohalf) {
            float fv = gsF[tid];
            float ov = gsO[tid];
            c = fmaf(fv, c, iv * gv);
            float h = ov * ftanh_fast(c);
            hs[tid] = h;
            if (shi) {
                size_t idx = (size_t)t * (BATCH * 256) + b * 256 + dir * 128 + tid;
                uint32_t ph = pack_bf2(h, 0.f);
                float res = h - bflo(ph);
                uint32_t pl = pack_bf2(res, 0.f);
                shi[idx] = (uint16_t)ph;
                slo[idx] = (uint16_t)pl;
            } else {
                out[dir * HID + (size_t)t * outT + (size_t)b * outB + tid] = h;
            }
        }
        __syncthreads();
        xg0 = xg0n;
        xg1 = xg1n;
    }
}

// ---------------- launch ------------------------------------------------------
extern "C" void kernel_launch(void* const* d_in, const int* in_sizes, int n_in,
                              void* d_out, int out_size)
{
    const float* x        = (const float*)d_in[0];
    // d_in[1] = lengths (unused, as in the reference)
    const float* Wih_fw1  = (const float*)d_in[2];
    const float* Whh_fw1  = (const float*)d_in[3];
    const float* bih_fw1  = (const float*)d_in[4];
    const float* bhh_fw1  = (const float*)d_in[5];
    const float* Wih_bw1  = (const float*)d_in[6];
    const float* Whh_bw1  = (const float*)d_in[7];
    const float* bih_bw1  = (const float*)d_in[8];
    const float* bhh_bw1  = (const float*)d_in[9];
    const float* Wih_fw2  = (const float*)d_in[10];
    const float* Whh_fw2  = (const float*)d_in[11];
    const float* bih_fw2  = (const float*)d_in[12];
    const float* bhh_fw2  = (const float*)d_in[13];
    const float* Wih_bw2  = (const float*)d_in[14];
    const float* Whh_bw2  = (const float*)d_in[15];
    const float* bih_bw2  = (const float*)d_in[16];
    const float* bhh_bw2  = (const float*)d_in[17];
    float* out = (float*)d_out;

    float *xg;
    uint16_t *ahi, *alo, *whi, *wlo;
    cudaGetSymbolAddress((void**)&xg,  g_xg);
    cudaGetSymbolAddress((void**)&ahi, g_ahi);
    cudaGetSymbolAddress((void**)&alo, g_alo);
    cudaGetSymbolAddress((void**)&whi, g_whi);
    cudaGetSymbolAddress((void**)&wlo, g_wlo);

    cudaFuncSetAttribute(lstm_rec2, cudaFuncAttributeMaxDynamicSharedMemorySize,
                         REC2_SMEM);
    cudaFuncSetAttribute(gemm_tc, cudaFuncAttributeMaxDynamicSharedMemorySize,
                         GEMM_SMEM);

    const int M = TSEQ * BATCH;          // 65536

    // 0) one-time weight splits (tiny)
    conv_split<<<(512 * 128 / 4 + 255) / 256, 256>>>(
        (const float4*)Wih_fw1, (uint2*)(whi + WOFF_FW1), (uint2*)(wlo + WOFF_FW1), 512 * 128 / 4);
    conv_split<<<(512 * 128 / 4 + 255) / 256, 256>>>(
        (const float4*)Wih_bw1, (uint2*)(whi + WOFF_BW1), (uint2*)(wlo + WOFF_BW1), 512 * 128 / 4);
    conv_split<<<(512 * 256 / 4 + 255) / 256, 256>>>(
        (const float4*)Wih_fw2, (uint2*)(whi + WOFF_FW2), (uint2*)(wlo + WOFF_FW2), 512 * 256 / 4);
    conv_split<<<(512 * 256 / 4 + 255) / 256, 256>>>(
        (const float4*)Wih_bw2, (uint2*)(whi + WOFF_BW2), (uint2*)(wlo + WOFF_BW2), 512 * 256 / 4);

    // 1) x: transpose + split -> Ahi/Alo [T*B, 128]
    conv_x<<<(TSEQ * BATCH * 32 + 255) / 256, 256>>>(
        (const float4*)x, (uint2*)ahi, (uint2*)alo);

    // 2) layer-1 input projections (tensor cores; bias folded in)
    dim3 gg(M / 128, G4 / 128);
    gemm_tc<<<gg, 256, GEMM_SMEM>>>(ahi, alo, whi + WOFF_FW1, wlo + WOFF_FW1,
                                    bih_fw1, bhh_fw1, xg,          128);
    gemm_tc<<<gg, 256, GEMM_SMEM>>>(ahi, alo, whi + WOFF_BW1, wlo + WOFF_BW1,
                                    bih_bw1, bhh_bw1, xg + XGHALF, 128);

    // 3) layer-1 recurrence -> bf16 hi/lo split directly into Ahi/Alo [T*B,256]
    lstm_rec2<<<dim3(BATCH, 2), 256, REC2_SMEM>>>(
        xg, Whh_fw1, Whh_bw1, nullptr, 0, 0, ahi, alo);

    // 4) layer-2 input projections (K = 256)
    gemm_tc<<<gg, 256, GEMM_SMEM>>>(ahi, alo, whi + WOFF_FW2, wlo + WOFF_FW2,
                                    bih_fw2, bhh_fw2, xg,          256);
    gemm_tc<<<gg, 256, GEMM_SMEM>>>(ahi, alo, whi + WOFF_BW2, wlo + WOFF_BW2,
                                    bih_bw2, bhh_bw2, xg + XGHALF, 256);

    // 5) layer-2 recurrence -> d_out [B,T,256] (fp32)
    lstm_rec2<<<dim3(BATCH, 2), 256, REC2_SMEM>>>(
        xg, Whh_fw2, Whh_bw2, out, 256, TSEQ * 256, nullptr, nullptr);
}

// round 12
// speedup vs baseline: 1.8044x; 1.0038x over previous
#include <cuda_runtime.h>
#include <cuda_bf16.h>
#include <cstdint>

// Problem constants
#define TSEQ 1024
#define BATCH 64
#define HID 128
#define G4 512            // 4*HID
#define XGHALF (TSEQ*BATCH*G4)   // per-direction xg elements

// ---------------- scratch (static device globals; no allocations) -------------
__device__ float g_xg[2 * TSEQ * BATCH * G4];     // [dir][T][B][512]
__device__ uint16_t g_ahi[TSEQ * BATCH * 256];    // A hi (bf16), layer 1 or 2
__device__ uint16_t g_alo[TSEQ * BATCH * 256];    // A lo (bf16)
__device__ uint16_t g_whi[512 * 768];             // W hi: fw1|bw1|fw2|bw2
__device__ uint16_t g_wlo[512 * 768];             // W lo

// W offsets (bf16 elements) — fw1:128 cols, bw1:128, fw2:256, bw2:256
#define WOFF_FW1 0
#define WOFF_BW1 (512 * 128)
#define WOFF_FW2 (512 * 256)
#define WOFF_BW2 (512 * 512)

// ---------------- MUFU activations (short chains; limits exact at +/-inf) -----
__device__ __forceinline__ float fsig_mufu(float x) {
    float e;
    asm("ex2.approx.f32 %0, %1;" : "=f"(e) : "f"(-1.4426950408889634f * x));
    float r;
    asm("rcp.approx.f32 %0, %1;" : "=f"(r) : "f"(1.0f + e));
    return r;
}
__device__ __forceinline__ float ftanh_mufu(float x) {
    float e;
    asm("ex2.approx.f32 %0, %1;" : "=f"(e) : "f"(-2.8853900817779268f * x));
    float r;
    asm("rcp.approx.f32 %0, %1;" : "=f"(r) : "f"(1.0f + e));
    return fmaf(2.0f, r, -1.0f);
}

// ---------------- bf16 pack/unpack --------------------------------------------
__device__ __forceinline__ uint32_t pack_bf2(float lo, float hi) {
    uint32_t r;   // PTX: cvt.rn.bf16x2.f32 d, a(high), b(low)
    asm("cvt.rn.bf16x2.f32 %0, %1, %2;" : "=r"(r) : "f"(hi), "f"(lo));
    return r;
}
__device__ __forceinline__ float bflo(uint32_t b) {
    return __int_as_float((int)(b << 16));
}
__device__ __forceinline__ float bfhi(uint32_t b) {
    return __int_as_float((int)(b & 0xFFFF0000u));
}
__device__ __forceinline__ void split4(float4 v, uint2& hi, uint2& lo) {
    uint32_t h0 = pack_bf2(v.x, v.y), h1 = pack_bf2(v.z, v.w);
    uint32_t l0 = pack_bf2(v.x - bflo(h0), v.y - bfhi(h0));
    uint32_t l1 = pack_bf2(v.z - bflo(h1), v.w - bfhi(h1));
    hi = make_uint2(h0, h1);
    lo = make_uint2(l0, l1);
}

// ---------------- warp-MMA primitives (baseline PTX, sm_80+) -------------------
__device__ __forceinline__ uint32_t smem_u32(const void* p) {
    uint32_t a;
    asm("{ .reg .u64 t; cvta.to.shared.u64 t, %1; cvt.u32.u64 %0, t; }"
        : "=r"(a) : "l"(p));
    return a;
}
__device__ __forceinline__ void ldmx4(uint32_t* r, uint32_t addr) {
    asm volatile("ldmatrix.sync.aligned.m8n8.x4.shared.b16 {%0,%1,%2,%3}, [%4];"
                 : "=r"(r[0]), "=r"(r[1]), "=r"(r[2]), "=r"(r[3]) : "r"(addr));
}
__device__ __forceinline__ void mma16816(float* c, const uint32_t* a,
                                         const uint32_t* b) {
    asm volatile(
        "mma.sync.aligned.m16n8k16.row.col.f32.bf16.bf16.f32 "
        "{%0,%1,%2,%3}, {%4,%5,%6,%7}, {%8,%9}, {%0,%1,%2,%3};"
        : "+f"(c[0]), "+f"(c[1]), "+f"(c[2]), "+f"(c[3])
        : "r"(a[0]), "r"(a[1]), "r"(a[2]), "r"(a[3]), "r"(b[0]), "r"(b[1]));
}
__device__ __forceinline__ void cp16(uint32_t dst, const void* src) {
    asm volatile("cp.async.ca.shared.global [%0], [%1], 16;"
                 :: "r"(dst), "l"(src));
}
#define CP_COMMIT() asm volatile("cp.async.commit_group;" ::: "memory")
#define CP_WAIT0()  asm volatile("cp.async.wait_group 0;" ::: "memory")
// SW128-style swizzle for 128B-row tiles (row stride 128B = 64 bf16)
__device__ __forceinline__ uint32_t swz(uint32_t off) {
    return off ^ ((off >> 3) & 0x70);
}

// ---------------- converters ---------------------------------------------------
// x [B,T,128] -> (transpose to [T,B,128]) hi/lo bf16
__global__ void conv_x(const float4* __restrict__ x,
                       uint2* __restrict__ hi, uint2* __restrict__ lo) {
    int i = blockIdx.x * blockDim.x + threadIdx.x;   // over T*B*32 float4s
    if (i >= TSEQ * BATCH * 32) return;
    int t  = i >> 11;
    int r  = i & 2047;
    int b  = r >> 5;
    int k4 = r & 31;
    float4 v = x[((size_t)b * TSEQ + t) * 32 + k4];
    split4(v, hi[i], lo[i]);
}
// generic fp32 -> bf16 hi/lo split (n4 float4s)
__global__ void conv_split(const float4* __restrict__ src,
                           uint2* __restrict__ hi, uint2* __restrict__ lo,
                           int n4) {
    int i = blockIdx.x * blockDim.x + threadIdx.x;
    if (i >= n4) return;
    split4(src[i], hi[i], lo[i]);
}

// ---------------- tensor-core GEMM (bf16 pre-split, cp.async pipeline) ---------
// C[M,512] = A[M,K]*W[512,K]^T + bias1 + bias2.  Per CTA: 128x128 C-tile,
// 8 warps in 2(m)x4(n), each 64x32 via m16n8k16. K staged 64/iter, double-buffered.
#define KSTAGE 64
#define TILE_BY (128 * KSTAGE * 2)     // 16384 B per bf16 tile
#define STAGE_BY (4 * TILE_BY)         // AH, AL, BH, BL = 64 KB
#define GEMM_SMEM (2 * STAGE_BY)       // double buffer = 128 KB

__global__ __launch_bounds__(256, 1) void gemm_tc(
    const uint16_t* __restrict__ Ahi, const uint16_t* __restrict__ Alo,
    const uint16_t* __restrict__ Whi, const uint16_t* __restrict__ Wlo,
    const float* __restrict__ bias1, const float* __restrict__ bias2,
    float* __restrict__ C, int K)
{
    extern __shared__ __align__(1024) char smem[];
    uint32_t sb = smem_u32(smem);

    int tid = threadIdx.x;
    int wid = tid >> 5;
    int l   = tid & 31;
    int wm  = wid >> 2;          // 0..1  (64-row slab)
    int wn  = wid & 3;           // 0..3  (32-col slab)
    int bm  = blockIdx.x * 128;
    int bn  = blockIdx.y * 128;

    float acc[4][4][4];
#pragma unroll
    for (int i = 0; i < 4; i++)
#pragma unroll
        for (int jj = 0; jj < 4; jj++)
#pragma unroll
            for (int e = 0; e < 4; e++) acc[i][jj][e] = 0.f;

    // loader: thread -> row tid>>1, four 16B chunks at col-chunks (tid&1)*4+q
    int lrow = tid >> 1;
    const uint16_t* Arow_h = Ahi + (size_t)(bm + lrow) * K;
    const uint16_t* Arow_l = Alo + (size_t)(bm + lrow) * K;
    const uint16_t* Wrow_h = Whi + (size_t)(bn + lrow) * K;
    const uint16_t* Wrow_l = Wlo + (size_t)(bn + lrow) * K;

    // ldmatrix lane address components (within a 128x64 tile)
    int a_row = (l & 7) + ((l >> 3) & 1) * 8;
    int a_cb  = ((l >> 4) & 1) * 8;
    int b_row = (l & 7) + ((l >> 4) & 1) * 8;
    int b_cb  = ((l >> 3) & 1) * 8;

    int nst = K / KSTAGE;

    // --- stage loader (cp.async, 16 chunks per thread) ---
#define LOAD_STAGE(st, buf)                                                   \
    do {                                                                      \
        uint32_t base_ = sb + (buf) * STAGE_BY;                               \
        int k0_ = (st) * KSTAGE;                                              \
        _Pragma("unroll")                                                     \
        for (int q_ = 0; q_ < 4; q_++) {                                      \
            int c8_ = (tid & 1) * 4 + q_;                                     \
            uint32_t d_ = swz((uint32_t)(lrow * 128 + c8_ * 16));             \
            int so_ = k0_ + c8_ * 8;                                          \
            cp16(base_ + 0 * TILE_BY + d_, Arow_h + so_);                     \
            cp16(base_ + 1 * TILE_BY + d_, Arow_l + so_);                     \
            cp16(base_ + 2 * TILE_BY + d_, Wrow_h + so_);                     \
            cp16(base_ + 3 * TILE_BY + d_, Wrow_l + so_);                     \
        }                                                                     \
        CP_COMMIT();                                                          \
    } while (0)

    LOAD_STAGE(0, 0);

    for (int st = 0; st < nst; st++) {
        int buf = st & 1;
        CP_WAIT0();
        __syncthreads();
        if (st + 1 < nst) LOAD_STAGE(st + 1, buf ^ 1);

        uint32_t sAH = sb + buf * STAGE_BY;
        uint32_t sAL = sAH + TILE_BY;
        uint32_t sBH = sAH + 2 * TILE_BY;
        uint32_t sBL = sAH + 3 * TILE_BY;

#pragma unroll
        for (int kk = 0; kk < KSTAGE / 16; kk++) {
            int C0 = kk * 16;
            uint32_t bh[8], bl[8];
#pragma unroll
            for (int half = 0; half < 2; half++) {
                uint32_t off = swz((uint32_t)(
                    (wn * 32 + half * 16 + b_row) * 128 + (C0 + b_cb) * 2));
                ldmx4(bh + half * 4, sBH + off);
                ldmx4(bl + half * 4, sBL + off);
            }
#pragma unroll
            for (int mt = 0; mt < 4; mt++) {
                uint32_t off = swz((uint32_t)(
                    (wm * 64 + mt * 16 + a_row) * 128 + (C0 + a_cb) * 2));
                uint32_t ah[4], al[4];
                ldmx4(ah, sAH + off);
                ldmx4(al, sAL + off);
#pragma unroll
                for (int nt = 0; nt < 4; nt++) {
                    mma16816(acc[mt][nt], ah, bh + nt * 2);
                    mma16816(acc[mt][nt], al, bh + nt * 2);
                    mma16816(acc[mt][nt], ah, bl + nt * 2);
                }
            }
        }
        __syncthreads();
    }

    // epilogue: bias + store
    int crow = l >> 2;
    int ccol = (l & 3) * 2;
#pragma unroll
    for (int nt = 0; nt < 4; nt++) {
        int gc = bn + wn * 32 + nt * 8 + ccol;
        float b0 = __ldg(&bias1[gc])     + __ldg(&bias2[gc]);
        float b1 = __ldg(&bias1[gc + 1]) + __ldg(&bias2[gc + 1]);
#pragma unroll
        for (int mt = 0; mt < 4; mt++) {
            int gr = bm + wm * 64 + mt * 16 + crow;
            float* p0 = C + (size_t)gr * G4 + gc;
            p0[0] = acc[mt][nt][0] + b0;
            p0[1] = acc[mt][nt][1] + b1;
            float* p1 = C + (size_t)(gr + 8) * G4 + gc;
            p1[0] = acc[mt][nt][2] + b0;
            p1[1] = acc[mt][nt][3] + b1;
        }
    }
}

// ---------------- recurrent LSTM scan: 256 threads, 2 gate-rows per thread -----
// Thread tid owns rows tid and tid+256:
//   tid<128:   row tid   = gate i (sigmoid),  row tid+256 = gate g (tanh)
//   tid>=128:  row tid   = gate f (sigmoid),  row tid+256 = gate o (sigmoid)
// h quads loaded once per thread feed both rows. Whh cols 0..RK2-1 in regs,
// cols RK2..127 in smem (transposed quads, conflict-free LDS.128).
#define RK2 88
#define SKQ2 ((128 - RK2) / 4)          // 10 smem quads per row
#define REC2_SMEM (SKQ2 * G4 * 16 + (HID + 2 * HID) * 4)

__global__ __launch_bounds__(256, 1) void lstm_rec2(
    const float* __restrict__ xg,        // [dir][T][B][512]
    const float* __restrict__ Whh0,      // fw weights [512][128]
    const float* __restrict__ Whh1,      // bw weights [512][128]
    float* __restrict__ out,             // fp32 h output (layer 2) or unused
    int outT, int outB,                  // strides (floats) for t and b
    uint16_t* __restrict__ shi,          // if non-null: write bf16 hi/lo split
    uint16_t* __restrict__ slo)          //   at [t][b][dir*128+j] (layer 1)
{
    extern __shared__ float sm[];
    float4* ws4 = (float4*)sm;                   // SKQ2*512 quads: [q][row]
    float* hs  = sm + SKQ2 * 4 * G4;             // 128 (16B aligned)
    float* gsF = hs + HID;                       // 128 (f gate)
    float* gsO = gsF + HID;                      // 128 (o gate)

    int tid = threadIdx.x;
    int b   = blockIdx.x;
    int dir = blockIdx.y;
    const float* Whh = dir ? Whh1 : Whh0;
    int r0 = tid, r1 = tid + 256;

    const float4* W0 = (const float4*)(Whh + (size_t)r0 * 128);
    const float4* W1 = (const float4*)(Whh + (size_t)r1 * 128);
    float w0[RK2], w1[RK2];
#pragma unroll
    for (int q = 0; q < RK2 / 4; q++) {
        float4 v = W0[q];
        w0[4 * q + 0] = v.x; w0[4 * q + 1] = v.y;
        w0[4 * q + 2] = v.z; w0[4 * q + 3] = v.w;
        v = W1[q];
        w1[4 * q + 0] = v.x; w1[4 * q + 1] = v.y;
        w1[4 * q + 2] = v.z; w1[4 * q + 3] = v.w;
    }
#pragma unroll
    for (int q = RK2 / 4; q < 32; q++) {
        ws4[(q - RK2 / 4) * G4 + r0] = W0[q];
        ws4[(q - RK2 / 4) * G4 + r1] = W1[q];
    }

    if (tid < HID) hs[tid] = 0.f;
    float c = 0.f;
    __syncthreads();

    const float4* hs4 = (const float4*)hs;
    size_t xgb0 = (size_t)dir * XGHALF + (size_t)b * G4 + r0;
    size_t xgb1 = xgb0 + 256;
    int t0 = dir ? (TSEQ - 1) : 0;
    float xg0 = __ldg(xg + xgb0 + (size_t)t0 * (BATCH * G4));
    float xg1 = __ldg(xg + xgb1 + (size_t)t0 * (BATCH * G4));
    bool lohalf = (tid < HID);

    for (int s = 0; s < TSEQ; s++) {
        int t = dir ? (TSEQ - 1 - s) : s;
        int tn = dir ? max(t - 1, 0) : min(t + 1, TSEQ - 1);
        float xg0n = __ldg(xg + xgb0 + (size_t)tn * (BATCH * G4));
        float xg1n = __ldg(xg + xgb1 + (size_t)tn * (BATCH * G4));

        float a0 = xg0, a1 = 0.f, a2 = 0.f, a3 = 0.f;
        float b0 = xg1, b1 = 0.f, b2 = 0.f, b3 = 0.f;
#pragma unroll
        for (int q = 0; q < RK2 / 4; q++) {      // register half, both rows
            float4 hv = hs4[q];
            a0 += w0[4 * q + 0] * hv.x;
            a1 += w0[4 * q + 1] * hv.y;
            a2 += w0[4 * q + 2] * hv.z;
            a3 += w0[4 * q + 3] * hv.w;
            b0 += w1[4 * q + 0] * hv.x;
            b1 += w1[4 * q + 1] * hv.y;
            b2 += w1[4 * q + 2] * hv.z;
            b3 += w1[4 * q + 3] * hv.w;
        }
#pragma unroll
        for (int q = 0; q < SKQ2; q++) {         // smem half, both rows
            float4 hv = hs4[RK2 / 4 + q];
            float4 u = ws4[q * G4 + r0];
            float4 v = ws4[q * G4 + r1];
            a0 += u.x * hv.x; a1 += u.y * hv.y;
            a2 += u.z * hv.z; a3 += u.w * hv.w;
            b0 += v.x * hv.x; b1 += v.y * hv.y;
            b2 += v.z * hv.z; b3 += v.w * hv.w;
        }
        float pre0 = (a0 + a1) + (a2 + a3);      // gate i (tid<128) / f
        float pre1 = (b0 + b1) + (b2 + b3);      // gate g (tid<128) / o

        float v0 = fsig_mufu(pre0);
        float v1, iv = 0.f, gv = 0.f;
        if (lohalf) {
            v1 = ftanh_mufu(pre1);               // g
            iv = v0; gv = v1;
        } else {
            v1 = fsig_mufu(pre1);                // o
            gsF[tid - HID] = v0;
            gsO[tid - HID] = v1;
        }
        __syncthreads();

        if (lohalf) {
            float fv = gsF[tid];
            float ov = gsO[tid];
            c = fmaf(fv, c, iv * gv);
            float h = ov * ftanh_mufu(c);
            hs[tid] = h;
            if (shi) {
                size_t idx = (size_t)t * (BATCH * 256) + b * 256 + dir * 128 + tid;
                uint32_t ph = pack_bf2(h, 0.f);
                float res = h - bflo(ph);
                uint32_t pl = pack_bf2(res, 0.f);
                shi[idx] = (uint16_t)ph;
                slo[idx] = (uint16_t)pl;
            } else {
                out[dir * HID + (size_t)t * outT + (size_t)b * outB + tid] = h;
            }
        }
        __syncthreads();
        xg0 = xg0n;
        xg1 = xg1n;
    }
}

// ---------------- launch ------------------------------------------------------
extern "C" void kernel_launch(void* const* d_in, const int* in_sizes, int n_in,
                              void* d_out, int out_size)
{
    const float* x        = (const float*)d_in[0];
    // d_in[1] = lengths (unused, as in the reference)
    const float* Wih_fw1  = (const float*)d_in[2];
    const float* Whh_fw1  = (const float*)d_in[3];
    const float* bih_fw1  = (const float*)d_in[4];
    const float* bhh_fw1  = (const float*)d_in[5];
    const float* Wih_bw1  = (const float*)d_in[6];
    const float* Whh_bw1  = (const float*)d_in[7];
    const float* bih_bw1  = (const float*)d_in[8];
    const float* bhh_bw1  = (const float*)d_in[9];
    const float* Wih_fw2  = (const float*)d_in[10];
    const float* Whh_fw2  = (const float*)d_in[11];
    const float* bih_fw2  = (const float*)d_in[12];
    const float* bhh_fw2  = (const float*)d_in[13];
    const float* Wih_bw2  = (const float*)d_in[14];
    const float* Whh_bw2  = (const float*)d_in[15];
    const float* bih_bw2  = (const float*)d_in[16];
    const float* bhh_bw2  = (const float*)d_in[17];
    float* out = (float*)d_out;

    float *xg;
    uint16_t *ahi, *alo, *whi, *wlo;
    cudaGetSymbolAddress((void**)&xg,  g_xg);
    cudaGetSymbolAddress((void**)&ahi, g_ahi);
    cudaGetSymbolAddress((void**)&alo, g_alo);
    cudaGetSymbolAddress((void**)&whi, g_whi);
    cudaGetSymbolAddress((void**)&wlo, g_wlo);

    cudaFuncSetAttribute(lstm_rec2, cudaFuncAttributeMaxDynamicSharedMemorySize,
                         REC2_SMEM);
    cudaFuncSetAttribute(gemm_tc, cudaFuncAttributeMaxDynamicSharedMemorySize,
                         GEMM_SMEM);

    const int M = TSEQ * BATCH;          // 65536

    // 0) one-time weight splits (tiny)
    conv_split<<<(512 * 128 / 4 + 255) / 256, 256>>>(
        (const float4*)Wih_fw1, (uint2*)(whi + WOFF_FW1), (uint2*)(wlo + WOFF_FW1), 512 * 128 / 4);
    conv_split<<<(512 * 128 / 4 + 255) / 256, 256>>>(
        (const float4*)Wih_bw1, (uint2*)(whi + WOFF_BW1), (uint2*)(wlo + WOFF_BW1), 512 * 128 / 4);
    conv_split<<<(512 * 256 / 4 + 255) / 256, 256>>>(
        (const float4*)Wih_fw2, (uint2*)(whi + WOFF_FW2), (uint2*)(wlo + WOFF_FW2), 512 * 256 / 4);
    conv_split<<<(512 * 256 / 4 + 255) / 256, 256>>>(
        (const float4*)Wih_bw2, (uint2*)(whi + WOFF_BW2), (uint2*)(wlo + WOFF_BW2), 512 * 256 / 4);

    // 1) x: transpose + split -> Ahi/Alo [T*B, 128]
    conv_x<<<(TSEQ * BATCH * 32 + 255) / 256, 256>>>(
        (const float4*)x, (uint2*)ahi, (uint2*)alo);

    // 2) layer-1 input projections (tensor cores; bias folded in)
    dim3 gg(M / 128, G4 / 128);
    gemm_tc<<<gg, 256, GEMM_SMEM>>>(ahi, alo, whi + WOFF_FW1, wlo + WOFF_FW1,
                                    bih_fw1, bhh_fw1, xg,          128);
    gemm_tc<<<gg, 256, GEMM_SMEM>>>(ahi, alo, whi + WOFF_BW1, wlo + WOFF_BW1,
                                    bih_bw1, bhh_bw1, xg + XGHALF, 128);

    // 3) layer-1 recurrence -> bf16 hi/lo split directly into Ahi/Alo [T*B,256]
    lstm_rec2<<<dim3(BATCH, 2), 256, REC2_SMEM>>>(
        xg, Whh_fw1, Whh_bw1, nullptr, 0, 0, ahi, alo);

    // 4) layer-2 input projections (K = 256)
    gemm_tc<<<gg, 256, GEMM_SMEM>>>(ahi, alo, whi + WOFF_FW2, wlo + WOFF_FW2,
                                    bih_fw2, bhh_fw2, xg,          256);
    gemm_tc<<<gg, 256, GEMM_SMEM>>>(ahi, alo, whi + WOFF_BW2, wlo + WOFF_BW2,
                                    bih_bw2, bhh_bw2, xg + XGHALF, 256);

    // 5) layer-2 recurrence -> d_out [B,T,256] (fp32)
    lstm_rec2<<<dim3(BATCH, 2), 256, REC2_SMEM>>>(
        xg, Whh_fw2, Whh_bw2, out, 256, TSEQ * 256, nullptr, nullptr);
}